// round 3
// baseline (speedup 1.0000x reference)
#include <cuda_runtime.h>
#include <math.h>

#define Bsz 2
#define Ssz 2048
#define Dsz 1024
#define Hsz 16
#define DHsz 64
#define Rsz 256
#define NKk 4096
#define NSLICE 32

// ---------------- single scratch arena (one symbol, no allocations) ---------
#define OFF_NX    ((size_t)0)                         // B*S*D = 4194304
#define OFF_NX2   (OFF_NX   + (size_t)Bsz*Ssz*Dsz)    // 4194304
#define OFF_SC    (OFF_NX2  + (size_t)Bsz*Ssz*Dsz)    // B*D*R = 524288
#define OFF_MC    (OFF_SC   + (size_t)Bsz*Dsz*Rsz)    // 524288
#define OFF_E     (OFF_MC   + (size_t)Bsz*Dsz*Rsz)    // 3*B*R*D = 1572864
#define OFF_H     (OFF_E    + (size_t)3*Bsz*Rsz*Dsz)  // B*S*R = 1048576
#define OFF_QM    (OFF_H    + (size_t)Bsz*Ssz*Rsz)    // 1048576
#define OFF_QKV   (OFF_QM   + (size_t)Bsz*Ssz*Rsz)    // 3*B*S*D = 12582912
#define OFF_AO    (OFF_QKV  + (size_t)3*Bsz*Ssz*Dsz)  // 4194304
#define OFF_MS    (OFF_AO   + (size_t)Bsz*Ssz*Dsz)    // B*S*NK = 16777216
#define OFF_ACC   (OFF_MS   + (size_t)Bsz*Ssz*NKk)    // 5120
#define OFF_W     (OFF_ACC  + (size_t)NSLICE*Bsz*5*16)// 160
#define SCRATCH_TOTAL (OFF_W + (size_t)Bsz*5*16)

__device__ float g_scratch[SCRATCH_TOTAL];

// ---------------- zero router accumulators ----------------------------------
__global__ void zero_kernel(float* p, int n) {
    int i = blockIdx.x*256 + threadIdx.x;
    if (i < n) p[i] = 0.f;
}

// ---------------- LayerNorm + router logits + importance-pooled softmax -----
__global__ __launch_bounds__(256) void ln_route_kernel(
    const float* __restrict__ X, const float* __restrict__ imp,
    const float* __restrict__ W0, const float* __restrict__ W1,
    const float* __restrict__ W2, const float* __restrict__ W3,
    const float* __restrict__ gamma, const float* __restrict__ beta,
    float* __restrict__ NX, float* __restrict__ accPart,
    int nR, int rbase)
{
    int s = blockIdx.x, b = blockIdx.y, tid = threadIdx.x;
    int lane = tid & 31, wid = tid >> 5;
    const float* xr = X + ((size_t)b*Ssz + s)*Dsz;
    __shared__ float xs[Dsz];
    __shared__ float red[32];
    __shared__ float lg[64];
    float lsum = 0.f, lsq = 0.f;
    for (int i = tid; i < Dsz; i += 256) {
        float v = xr[i]; xs[i] = v; lsum += v; lsq += v*v;
    }
    #pragma unroll
    for (int o = 16; o > 0; o >>= 1) {
        lsum += __shfl_down_sync(0xffffffffu, lsum, o);
        lsq  += __shfl_down_sync(0xffffffffu, lsq,  o);
    }
    if (lane == 0) { red[wid] = lsum; red[8+wid] = lsq; }
    __syncthreads();
    if (tid == 0) {
        float ssum = 0.f, sq = 0.f;
        #pragma unroll
        for (int w = 0; w < 8; w++) { ssum += red[w]; sq += red[8+w]; }
        float mean = ssum / (float)Dsz;
        float var  = sq / (float)Dsz - mean*mean;
        red[16] = mean; red[17] = rsqrtf(var + 1e-5f);
    }
    __syncthreads();
    float mean = red[16], rstd = red[17];
    float* nxr = NX + ((size_t)b*Ssz + s)*Dsz;
    for (int i = tid; i < Dsz; i += 256) {
        float v = (xs[i]-mean)*rstd*gamma[i] + beta[i];
        xs[i] = v; nxr[i] = v;
    }
    __syncthreads();
    // router logits: one warp per expert slot
    for (int e = wid; e < nR*16; e += 8) {
        const float* Wr = (e < 16 ? W0 : (e < 32 ? W1 : (e < 48 ? W2 : W3))) + (size_t)(e & 15)*Dsz;
        float acc = 0.f;
        for (int i = lane; i < Dsz; i += 32) acc += xs[i]*Wr[i];
        #pragma unroll
        for (int o = 16; o > 0; o >>= 1) acc += __shfl_down_sync(0xffffffffu, acc, o);
        if (lane == 0) lg[e] = acc;
    }
    __syncthreads();
    if (tid < nR) {
        float mx = -1e30f;
        #pragma unroll
        for (int e = 0; e < 16; e++) mx = fmaxf(mx, lg[tid*16+e]);
        float ex[16]; float se = 0.f;
        #pragma unroll
        for (int e = 0; e < 16; e++) { ex[e] = __expf(lg[tid*16+e]-mx); se += ex[e]; }
        float wi = imp[(size_t)b*Ssz + s] / se;
        int slice = s & (NSLICE-1);
        float* dst = accPart + ((size_t)(slice*Bsz + b)*5 + rbase + tid)*16;
        #pragma unroll
        for (int e = 0; e < 16; e++) atomicAdd(&dst[e], wi*ex[e]);
    }
}

// ---------------- reduce slices + normalize route weights -------------------
__global__ void finalize_w_kernel(const float* __restrict__ accPart,
                                  float* __restrict__ w, int rbase, int nR)
{
    __shared__ float vals[2*5*16];
    int t = threadIdx.x;
    int tot = Bsz*nR*16;
    if (t < tot) {
        int b = t/(nR*16); int r = (t/16) % nR; int e = t & 15;
        float sum = 0.f;
        for (int sl = 0; sl < NSLICE; sl++)
            sum += accPart[((size_t)(sl*Bsz + b)*5 + rbase + r)*16 + e];
        vals[t] = sum;
    }
    __syncthreads();
    if (t < tot) {
        int b = t/(nR*16); int r = (t/16) % nR;
        float den = 1e-8f;
        #pragma unroll
        for (int j = 0; j < 16; j++) den += vals[(b*nR + r)*16 + j];
        w[((b*5) + rbase + r)*16 + (t & 15)] = vals[t] / den;
    }
}

// ---------------- weighted pool combine: sc / mc ([16,D,R] -> [B,D,R]) ------
__global__ __launch_bounds__(256) void combine_c_kernel(
    const float* __restrict__ w, const float* __restrict__ pool,
    float* __restrict__ out, int router)
{
    __shared__ float ws[2][16];
    int tid = threadIdx.x;
    if (tid < 32) ws[tid/16][tid & 15] = w[((tid/16)*5 + router)*16 + (tid & 15)];
    __syncthreads();
    const int X = Dsz*Rsz;
    int i = blockIdx.x*256 + tid;
    if (i >= X) return;
    float a0 = 0.f, a1 = 0.f;
    #pragma unroll
    for (int n = 0; n < 16; n++) {
        float p = pool[(size_t)n*X + i];
        a0 += ws[0][n]*p; a1 += ws[1][n]*p;
    }
    out[i] = a0; out[(size_t)X + i] = a1;
}

// ---------------- expand combine: [16,R,D] -> [3][B][R,D] -------------------
__global__ __launch_bounds__(256) void combine_e_kernel(
    const float* __restrict__ w, const float* __restrict__ pool,
    float* __restrict__ out)
{
    __shared__ float ws[6][16];
    int tid = threadIdx.x;
    if (tid < 96) {
        int slot = tid/16, e = tid & 15;
        int r3 = slot/2, b = slot & 1;
        ws[slot][e] = w[(b*5 + 1 + r3)*16 + e];
    }
    __syncthreads();
    const int X = Rsz*Dsz;
    int i = blockIdx.x*256 + tid;
    if (i >= X) return;
    float a[6] = {0.f,0.f,0.f,0.f,0.f,0.f};
    #pragma unroll
    for (int n = 0; n < 16; n++) {
        float p = pool[(size_t)n*X + i];
        #pragma unroll
        for (int sl = 0; sl < 6; sl++) a[sl] += ws[sl][n]*p;
    }
    #pragma unroll
    for (int sl = 0; sl < 6; sl++) out[(size_t)sl*X + i] = a[sl];
}

// ---------------- SGEMM: C[M,N] = alpha * A[M,K] x B (+ residual) -----------
// BT=false: B is [K,N] row-major (NN).  BT=true: B is [N,K] row-major (NT).
template<bool BT, bool RESID>
__global__ __launch_bounds__(256) void sgemm_kernel(
    const float* __restrict__ A, const float* __restrict__ Bm,
    const float* __restrict__ Rsrc, float* __restrict__ C,
    int M, int N, int K, float alpha,
    size_t sA, size_t sB, size_t sC, size_t sR)
{
    A += (size_t)blockIdx.z * sA;
    Bm += (size_t)blockIdx.z * sB;
    C += (size_t)blockIdx.z * sC;
    if (RESID) Rsrc += (size_t)blockIdx.z * sR;

    __shared__ float Ast[8][128];
    __shared__ float Bs[8][128];
    int tid = threadIdx.x;
    int bm = blockIdx.y * 128, bn = blockIdx.x * 128;
    int tx = tid & 15, ty = tid >> 4;

    float acc[8][8];
    #pragma unroll
    for (int i = 0; i < 8; i++)
        #pragma unroll
        for (int j = 0; j < 8; j++) acc[i][j] = 0.f;

    int ar = tid >> 1, akp = (tid & 1)*4;

    for (int k0 = 0; k0 < K; k0 += 8) {
        float4 av = *(const float4*)&A[(size_t)(bm + ar)*K + k0 + akp];
        Ast[akp+0][ar] = av.x; Ast[akp+1][ar] = av.y;
        Ast[akp+2][ar] = av.z; Ast[akp+3][ar] = av.w;
        if (!BT) {
            int kk = tid >> 5, c4 = (tid & 31)*4;
            *(float4*)&Bs[kk][c4] = *(const float4*)&Bm[(size_t)(k0 + kk)*N + bn + c4];
        } else {
            int n = tid >> 1, kp = (tid & 1)*4;
            float4 bv = *(const float4*)&Bm[(size_t)(bn + n)*K + k0 + kp];
            Bs[kp+0][n] = bv.x; Bs[kp+1][n] = bv.y;
            Bs[kp+2][n] = bv.z; Bs[kp+3][n] = bv.w;
        }
        __syncthreads();
        #pragma unroll
        for (int kk = 0; kk < 8; kk++) {
            float a[8], bb[8];
            *(float4*)&a[0]  = *(float4*)&Ast[kk][ty*8];
            *(float4*)&a[4]  = *(float4*)&Ast[kk][ty*8+4];
            *(float4*)&bb[0] = *(float4*)&Bs[kk][tx*8];
            *(float4*)&bb[4] = *(float4*)&Bs[kk][tx*8+4];
            #pragma unroll
            for (int i = 0; i < 8; i++)
                #pragma unroll
                for (int j = 0; j < 8; j++) acc[i][j] = fmaf(a[i], bb[j], acc[i][j]);
        }
        __syncthreads();
    }
    #pragma unroll
    for (int i = 0; i < 8; i++) {
        size_t row = (size_t)(bm + ty*8 + i);
        #pragma unroll
        for (int j = 0; j < 8; j += 4) {
            int col = bn + tx*8 + j;
            float4 r;
            r.x = alpha*acc[i][j+0]; r.y = alpha*acc[i][j+1];
            r.z = alpha*acc[i][j+2]; r.w = alpha*acc[i][j+3];
            if (RESID) {
                float4 rv = *(const float4*)&Rsrc[row*N + col];
                r.x += rv.x; r.y += rv.y; r.z += rv.z; r.w += rv.w;
            }
            *(float4*)&C[row*N + col] = r;
        }
    }
}

// ---------------- causal flash attention (fp32, dh=64) ----------------------
__global__ __launch_bounds__(64) void flash_kernel(
    const float* __restrict__ Q, const float* __restrict__ Kt,
    const float* __restrict__ V, float* __restrict__ O)
{
    int qt = blockIdx.x, h = blockIdx.y, b = blockIdx.z;
    int t = threadIdx.x;
    int qr = qt*64 + t;
    const size_t base = ((size_t)b*Ssz)*Dsz + h*DHsz;

    float q[64];
    #pragma unroll
    for (int i = 0; i < 16; i++) {
        float4 v = *(const float4*)&Q[base + (size_t)qr*Dsz + i*4];
        q[4*i+0] = v.x*0.125f; q[4*i+1] = v.y*0.125f;
        q[4*i+2] = v.z*0.125f; q[4*i+3] = v.w*0.125f;
    }
    float acc[64];
    #pragma unroll
    for (int i = 0; i < 64; i++) acc[i] = 0.f;
    float m = -1e30f, l = 0.f;

    __shared__ float Ks[32][64];
    __shared__ float Vs[32][64];

    int ntiles = qt*2 + 2;
    for (int kt = 0; kt < ntiles; kt++) {
        int k0 = kt*32;
        #pragma unroll
        for (int i = 0; i < 8; i++) {
            int idx = t + i*64;        // float4 index over 512
            int row = idx >> 4, col4 = (idx & 15)*4;
            *(float4*)&Ks[row][col4] = *(const float4*)&Kt[base + (size_t)(k0+row)*Dsz + col4];
            *(float4*)&Vs[row][col4] = *(const float4*)&V [base + (size_t)(k0+row)*Dsz + col4];
        }
        __syncthreads();

        float s[32];
        float mnew = m;
        #pragma unroll
        for (int k = 0; k < 32; k++) {
            float d0 = 0.f, d1 = 0.f, d2 = 0.f, d3 = 0.f;
            #pragma unroll
            for (int i = 0; i < 16; i++) {
                float4 kv = *(const float4*)&Ks[k][i*4];
                d0 = fmaf(q[4*i+0], kv.x, d0);
                d1 = fmaf(q[4*i+1], kv.y, d1);
                d2 = fmaf(q[4*i+2], kv.z, d2);
                d3 = fmaf(q[4*i+3], kv.w, d3);
            }
            float d = (d0+d1)+(d2+d3);
            d = (k0 + k > qr) ? -1e30f : d;
            s[k] = d;
            mnew = fmaxf(mnew, d);
        }
        float corr = __expf(m - mnew);
        l *= corr;
        #pragma unroll
        for (int i = 0; i < 64; i++) acc[i] *= corr;
        #pragma unroll
        for (int k = 0; k < 32; k++) {
            float p = __expf(s[k] - mnew);
            l += p;
            #pragma unroll
            for (int i = 0; i < 16; i++) {
                float4 vv = *(const float4*)&Vs[k][i*4];
                acc[4*i+0] = fmaf(p, vv.x, acc[4*i+0]);
                acc[4*i+1] = fmaf(p, vv.y, acc[4*i+1]);
                acc[4*i+2] = fmaf(p, vv.z, acc[4*i+2]);
                acc[4*i+3] = fmaf(p, vv.w, acc[4*i+3]);
            }
        }
        m = mnew;
        __syncthreads();
    }
    float inv = 1.f / l;
    #pragma unroll
    for (int i = 0; i < 16; i++) {
        float4 r;
        r.x = acc[4*i+0]*inv; r.y = acc[4*i+1]*inv;
        r.z = acc[4*i+2]*inv; r.w = acc[4*i+3]*inv;
        *(float4*)&O[base + (size_t)qr*Dsz + i*4] = r;
    }
}

// ---------------- top-8 + softmax + knowledge gather + residual add ---------
__global__ __launch_bounds__(256) void topk_mem_kernel(
    const float* __restrict__ MS, const float* __restrict__ KV,
    float* __restrict__ OUT)
{
    int s = blockIdx.x, b = blockIdx.y, tid = threadIdx.x;
    __shared__ float sc[NKk];       // 16 KB
    __shared__ float rv[256];
    __shared__ int   ri[256];
    __shared__ float topv[8];
    __shared__ int   topi[8];
    __shared__ float tw[8];
    const float* row = MS + ((size_t)b*Ssz + s)*NKk;
    for (int i = tid; i < NKk; i += 256) sc[i] = row[i];
    __syncthreads();
    for (int it = 0; it < 8; it++) {
        float bv = -1e30f; int bi = NKk;
        for (int i = tid; i < NKk; i += 256) {
            float v = sc[i];
            if (v > bv) { bv = v; bi = i; }
        }
        rv[tid] = bv; ri[tid] = bi;
        __syncthreads();
        for (int off = 128; off > 0; off >>= 1) {
            if (tid < off) {
                if (rv[tid+off] > rv[tid] ||
                    (rv[tid+off] == rv[tid] && ri[tid+off] < ri[tid])) {
                    rv[tid] = rv[tid+off]; ri[tid] = ri[tid+off];
                }
            }
            __syncthreads();
        }
        if (tid == 0) { topv[it] = rv[0]; topi[it] = ri[0]; sc[ri[0]] = -1e30f; }
        __syncthreads();
    }
    if (tid == 0) {
        float mx = topv[0]; float se = 0.f;
        #pragma unroll
        for (int k = 0; k < 8; k++) { tw[k] = __expf(topv[k]-mx); se += tw[k]; }
        float inv = 1.f/se;
        #pragma unroll
        for (int k = 0; k < 8; k++) tw[k] *= inv;
    }
    __syncthreads();
    float w0 = tw[0], w1 = tw[1], w2 = tw[2], w3 = tw[3];
    float w4 = tw[4], w5 = tw[5], w6 = tw[6], w7 = tw[7];
    size_t i0 = (size_t)topi[0]*Dsz, i1 = (size_t)topi[1]*Dsz;
    size_t i2 = (size_t)topi[2]*Dsz, i3 = (size_t)topi[3]*Dsz;
    size_t i4 = (size_t)topi[4]*Dsz, i5 = (size_t)topi[5]*Dsz;
    size_t i6 = (size_t)topi[6]*Dsz, i7 = (size_t)topi[7]*Dsz;
    float* o = OUT + ((size_t)b*Ssz + s)*Dsz;
    for (int d = tid; d < Dsz; d += 256) {
        float a = o[d];
        a = fmaf(w0, KV[i0+d], a); a = fmaf(w1, KV[i1+d], a);
        a = fmaf(w2, KV[i2+d], a); a = fmaf(w3, KV[i3+d], a);
        a = fmaf(w4, KV[i4+d], a); a = fmaf(w5, KV[i5+d], a);
        a = fmaf(w6, KV[i6+d], a); a = fmaf(w7, KV[i7+d], a);
        o[d] = a;
    }
}

// ---------------- launch ----------------------------------------------------
extern "C" void kernel_launch(void* const* d_in, const int* in_sizes, int n_in,
                              void* d_out, int out_size)
{
    const float* x    = (const float*)d_in[0];
    const float* imp  = (const float*)d_in[1];
    const float* Wc   = (const float*)d_in[2];
    const float* WQ   = (const float*)d_in[3];
    const float* WK   = (const float*)d_in[4];
    const float* WV   = (const float*)d_in[5];
    const float* Wm   = (const float*)d_in[6];
    const float* cn   = (const float*)d_in[7];
    const float* pool = (const float*)d_in[8];
    const float* kK   = (const float*)d_in[9];
    const float* kV   = (const float*)d_in[10];
    const float* WO   = (const float*)d_in[11];
    const float* g1   = (const float*)d_in[12];
    const float* b1   = (const float*)d_in[13];
    const float* g2   = (const float*)d_in[14];
    const float* b2   = (const float*)d_in[15];
    float* out = (float*)d_out;

    static float* base = nullptr;
    if (!base) cudaGetSymbolAddress((void**)&base, g_scratch);

    float* nx   = base + OFF_NX;
    float* nx2  = base + OFF_NX2;
    float* scp  = base + OFF_SC;
    float* mcp  = base + OFF_MC;
    float* ep   = base + OFF_E;
    float* hp   = base + OFF_H;
    float* qmp  = base + OFF_QM;
    float* qkvp = base + OFF_QKV;
    float* aop  = base + OFF_AO;
    float* msp  = base + OFF_MS;
    float* accP = base + OFF_ACC;
    float* wptr = base + OFF_W;

    const size_t SD = (size_t)Ssz*Dsz;
    const size_t SR = (size_t)Ssz*Rsz;
    const size_t DR = (size_t)Dsz*Rsz;
    const size_t RD = (size_t)Rsz*Dsz;
    const size_t BSD = (size_t)Bsz*Ssz*Dsz;
    const size_t SNK = (size_t)Ssz*NKk;

    // 1) zero router accumulators
    zero_kernel<<<(NSLICE*Bsz*5*16 + 255)/256, 256>>>(accP, NSLICE*Bsz*5*16);
    // 2) LN1 + 4 routers
    ln_route_kernel<<<dim3(Ssz, Bsz), 256>>>(x, imp, Wc, WQ, WK, WV, g1, b1,
                                             nx, accP, 4, 0);
    finalize_w_kernel<<<1, 256>>>(accP, wptr, 0, 4);
    // 3) sc, e
    combine_c_kernel<<<(Dsz*Rsz)/256, 256>>>(wptr, cn, scp, 0);
    combine_e_kernel<<<(Rsz*Dsz)/256, 256>>>(wptr, pool, ep);
    // 4) h = nx @ sc      [2048,256] = [2048,1024] x [1024,256]
    sgemm_kernel<false,false><<<dim3(2,16,Bsz), 256>>>(nx, scp, nullptr, hp,
        Ssz, Rsz, Dsz, 1.f, SD, DR, SR, 0);
    // 5) Q/K/V = h @ e    [2048,1024] = [2048,256] x [256,1024]
    for (int r3 = 0; r3 < 3; r3++)
        sgemm_kernel<false,false><<<dim3(8,16,Bsz), 256>>>(hp, ep + (size_t)r3*Bsz*RD,
            nullptr, qkvp + (size_t)r3*BSD, Ssz, Dsz, Rsz, 1.f, SR, RD, SD, 0);
    // 6) attention
    flash_kernel<<<dim3(Ssz/64, Hsz, Bsz), 64>>>(qkvp, qkvp + BSD, qkvp + 2*BSD, aop);
    // 7) out = x + ao @ W_O^T
    sgemm_kernel<true,true><<<dim3(8,16,Bsz), 256>>>(aop, WO, x, out,
        Ssz, Dsz, Dsz, 1.f, SD, 0, SD, SD);
    // 8) LN2 + memory router
    ln_route_kernel<<<dim3(Ssz, Bsz), 256>>>(out, imp, Wm, Wm, Wm, Wm, g2, b2,
                                             nx2, accP, 1, 4);
    finalize_w_kernel<<<1, 256>>>(accP, wptr, 4, 1);
    // 9) mc, Qm
    combine_c_kernel<<<(Dsz*Rsz)/256, 256>>>(wptr, cn, mcp, 4);
    sgemm_kernel<false,false><<<dim3(2,16,Bsz), 256>>>(nx2, mcp, nullptr, qmp,
        Ssz, Rsz, Dsz, 1.f, SD, DR, SR, 0);
    // 10) ms = Qm @ knowledge_K^T / 16
    sgemm_kernel<true,false><<<dim3(32,16,Bsz), 256>>>(qmp, kK, nullptr, msp,
        Ssz, NKk, Rsz, 0.0625f, SR, 0, SNK, 0);
    // 11) top-8 + gather + residual
    topk_mem_kernel<<<dim3(Ssz, Bsz), 256>>>(msp, kV, out);
}

// round 4
// speedup vs baseline: 1.2973x; 1.2973x over previous
#include <cuda_runtime.h>
#include <math.h>
#include <stdint.h>

#define Bsz 2
#define Ssz 2048
#define Dsz 1024
#define Hsz 16
#define DHsz 64
#define Rsz 256
#define NKk 4096
#define NSLICE 32

// ---------------- single scratch arena (one symbol, no allocations) ---------
#define OFF_NX    ((size_t)0)
#define OFF_NX2   (OFF_NX   + (size_t)Bsz*Ssz*Dsz)
#define OFF_SC    (OFF_NX2  + (size_t)Bsz*Ssz*Dsz)    // scT [B][R][D]
#define OFF_MC    (OFF_SC   + (size_t)Bsz*Dsz*Rsz)    // mcT [B][R][D]
#define OFF_E     (OFF_MC   + (size_t)Bsz*Dsz*Rsz)    // eT  [3*B][D][R]
#define OFF_H     (OFF_E    + (size_t)3*Bsz*Rsz*Dsz)
#define OFF_QM    (OFF_H    + (size_t)Bsz*Ssz*Rsz)
#define OFF_QKV   (OFF_QM   + (size_t)Bsz*Ssz*Rsz)
#define OFF_AO    (OFF_QKV  + (size_t)3*Bsz*Ssz*Dsz)
#define OFF_MS    (OFF_AO   + (size_t)Bsz*Ssz*Dsz)
#define OFF_ACC   (OFF_MS   + (size_t)Bsz*Ssz*NKk)
#define OFF_W     (OFF_ACC  + (size_t)NSLICE*Bsz*5*16)
#define SCRATCH_TOTAL (OFF_W + (size_t)Bsz*5*16)

__device__ float g_scratch[SCRATCH_TOTAL];

// ---------------- zero router accumulators ----------------------------------
__global__ void zero_kernel(float* p, int n) {
    int i = blockIdx.x*256 + threadIdx.x;
    if (i < n) p[i] = 0.f;
}

// ---------------- LayerNorm + router logits + importance-pooled softmax -----
__global__ __launch_bounds__(256) void ln_route_kernel(
    const float* __restrict__ X, const float* __restrict__ imp,
    const float* __restrict__ W0, const float* __restrict__ W1,
    const float* __restrict__ W2, const float* __restrict__ W3,
    const float* __restrict__ gamma, const float* __restrict__ beta,
    float* __restrict__ NX, float* __restrict__ accPart,
    int nR, int rbase)
{
    int s = blockIdx.x, b = blockIdx.y, tid = threadIdx.x;
    int lane = tid & 31, wid = tid >> 5;
    const float* xr = X + ((size_t)b*Ssz + s)*Dsz;
    __shared__ float xs[Dsz];
    __shared__ float red[32];
    __shared__ float lg[64];
    float lsum = 0.f, lsq = 0.f;
    for (int i = tid; i < Dsz; i += 256) {
        float v = xr[i]; xs[i] = v; lsum += v; lsq += v*v;
    }
    #pragma unroll
    for (int o = 16; o > 0; o >>= 1) {
        lsum += __shfl_down_sync(0xffffffffu, lsum, o);
        lsq  += __shfl_down_sync(0xffffffffu, lsq,  o);
    }
    if (lane == 0) { red[wid] = lsum; red[8+wid] = lsq; }
    __syncthreads();
    if (tid == 0) {
        float ssum = 0.f, sq = 0.f;
        #pragma unroll
        for (int w = 0; w < 8; w++) { ssum += red[w]; sq += red[8+w]; }
        float mean = ssum / (float)Dsz;
        float var  = sq / (float)Dsz - mean*mean;
        red[16] = mean; red[17] = rsqrtf(var + 1e-5f);
    }
    __syncthreads();
    float mean = red[16], rstd = red[17];
    float* nxr = NX + ((size_t)b*Ssz + s)*Dsz;
    for (int i = tid; i < Dsz; i += 256) {
        float v = (xs[i]-mean)*rstd*gamma[i] + beta[i];
        xs[i] = v; nxr[i] = v;
    }
    __syncthreads();
    for (int e = wid; e < nR*16; e += 8) {
        const float* Wr = (e < 16 ? W0 : (e < 32 ? W1 : (e < 48 ? W2 : W3))) + (size_t)(e & 15)*Dsz;
        float acc = 0.f;
        for (int i = lane; i < Dsz; i += 32) acc += xs[i]*Wr[i];
        #pragma unroll
        for (int o = 16; o > 0; o >>= 1) acc += __shfl_down_sync(0xffffffffu, acc, o);
        if (lane == 0) lg[e] = acc;
    }
    __syncthreads();
    if (tid < nR) {
        float mx = -1e30f;
        #pragma unroll
        for (int e = 0; e < 16; e++) mx = fmaxf(mx, lg[tid*16+e]);
        float ex[16]; float se = 0.f;
        #pragma unroll
        for (int e = 0; e < 16; e++) { ex[e] = __expf(lg[tid*16+e]-mx); se += ex[e]; }
        float wi = imp[(size_t)b*Ssz + s] / se;
        int slice = s & (NSLICE-1);
        float* dst = accPart + ((size_t)(slice*Bsz + b)*5 + rbase + tid)*16;
        #pragma unroll
        for (int e = 0; e < 16; e++) atomicAdd(&dst[e], wi*ex[e]);
    }
}

// ---------------- reduce slices + normalize route weights -------------------
__global__ void finalize_w_kernel(const float* __restrict__ accPart,
                                  float* __restrict__ w, int rbase, int nR)
{
    __shared__ float vals[2*5*16];
    int t = threadIdx.x;
    int tot = Bsz*nR*16;
    if (t < tot) {
        int b = t/(nR*16); int r = (t/16) % nR; int e = t & 15;
        float sum = 0.f;
        for (int sl = 0; sl < NSLICE; sl++)
            sum += accPart[((size_t)(sl*Bsz + b)*5 + rbase + r)*16 + e];
        vals[t] = sum;
    }
    __syncthreads();
    if (t < tot) {
        int b = t/(nR*16); int r = (t/16) % nR;
        float den = 1e-8f;
        #pragma unroll
        for (int j = 0; j < 16; j++) den += vals[(b*nR + r)*16 + j];
        w[((b*5) + rbase + r)*16 + (t & 15)] = vals[t] / den;
    }
}

// ------- weighted pool combine TRANSPOSED: [16,D,R] -> scT [B][R][D] --------
__global__ __launch_bounds__(256) void combine_cT_kernel(
    const float* __restrict__ w, const float* __restrict__ pool,
    float* __restrict__ out, int router)
{
    __shared__ float ws[2][16];
    __shared__ float tile[2][32][33];
    int tid = threadIdx.x;
    if (tid < 32) ws[tid>>4][tid&15] = w[((tid>>4)*5 + router)*16 + (tid&15)];
    __syncthreads();
    int tx = tid & 31, ty = tid >> 5;
    int d0 = blockIdx.x*32, r0 = blockIdx.y*32;
    const size_t X = (size_t)Dsz*Rsz;
    #pragma unroll
    for (int dr = 0; dr < 4; dr++) {
        int dd = ty + dr*8;
        float a0 = 0.f, a1 = 0.f;
        #pragma unroll
        for (int n = 0; n < 16; n++) {
            float p = pool[(size_t)n*X + (size_t)(d0+dd)*Rsz + r0 + tx];
            a0 += ws[0][n]*p; a1 += ws[1][n]*p;
        }
        tile[0][dd][tx] = a0; tile[1][dd][tx] = a1;
    }
    __syncthreads();
    #pragma unroll
    for (int dr = 0; dr < 4; dr++) {
        int rr = ty + dr*8;
        out[(size_t)(r0+rr)*Dsz + d0 + tx]     = tile[0][tx][rr];
        out[X + (size_t)(r0+rr)*Dsz + d0 + tx] = tile[1][tx][rr];
    }
}

// ------- expand combine TRANSPOSED: [16,R,D] -> eT [3*B][D][R] --------------
__global__ __launch_bounds__(256) void combine_eT_kernel(
    const float* __restrict__ w, const float* __restrict__ pool,
    float* __restrict__ out)
{
    __shared__ float ws[6][16];
    __shared__ float tile[6][32][33];
    int tid = threadIdx.x;
    if (tid < 96) {
        int slot = tid>>4, e = tid&15;
        int r3 = slot>>1, b = slot&1;
        ws[slot][e] = w[(b*5 + 1 + r3)*16 + e];
    }
    __syncthreads();
    int tx = tid&31, ty = tid>>5;
    int d0 = blockIdx.x*32, r0 = blockIdx.y*32;
    const size_t X = (size_t)Rsz*Dsz;
    #pragma unroll
    for (int dr = 0; dr < 4; dr++) {
        int rr = ty + dr*8;
        float a[6] = {0.f,0.f,0.f,0.f,0.f,0.f};
        #pragma unroll
        for (int n = 0; n < 16; n++) {
            float p = pool[(size_t)n*X + (size_t)(r0+rr)*Dsz + d0+tx];
            #pragma unroll
            for (int sl = 0; sl < 6; sl++) a[sl] += ws[sl][n]*p;
        }
        #pragma unroll
        for (int sl = 0; sl < 6; sl++) tile[sl][rr][tx] = a[sl];
    }
    __syncthreads();
    #pragma unroll
    for (int dr = 0; dr < 4; dr++) {
        int dd = ty + dr*8;
        #pragma unroll
        for (int sl = 0; sl < 6; sl++)
            out[(size_t)sl*X + (size_t)(d0+dd)*Rsz + r0+tx] = tile[sl][tx][dd];
    }
}

// ---------------- tf32 tensor-core GEMM (NT): C = alpha*A[M,K] x B[N,K]^T ---
// 128x128 tile, 256 thr = 8 warps (2x4), warp tile 64x32, mma m16n8k8 tf32.
// Smem staged in fragment order [k8][tile][frag][thr].
template<bool RESID>
__global__ __launch_bounds__(256) void tgemm_kernel(
    const float* __restrict__ A, const float* __restrict__ Bm,
    const float* __restrict__ Rsrc, float* __restrict__ C,
    int M, int N, int K, float alpha,
    size_t sA, size_t sB, size_t sC, size_t sR)
{
    __shared__ uint32_t As[4*8*4*32];    // 4096 = [k8][mt8][frag4][thr32]
    __shared__ uint32_t Bs[4*16*2*32];   // 4096 = [k8][nt16][frag2][thr32]
    A += (size_t)blockIdx.z*sA; Bm += (size_t)blockIdx.z*sB;
    C += (size_t)blockIdx.z*sC; if (RESID) Rsrc += (size_t)blockIdx.z*sR;
    int tid = threadIdx.x, lane = tid&31, warp = tid>>5;
    int wm = warp>>2, wn = warp&3;
    int bm = blockIdx.y<<7, bn = blockIdx.x<<7;

    float c[4][4][4];
    #pragma unroll
    for (int i=0;i<4;i++)
        #pragma unroll
        for(int j=0;j<4;j++)
            #pragma unroll
            for(int f=0;f<4;f++) c[i][j][f]=0.f;

    int row = tid>>1;          // 0..127
    int qb  = (tid&1)*4;       // base float4 index along k
    const float* Aro = A + (size_t)(bm+row)*K;
    const float* Bro = Bm + (size_t)(bn+row)*K;
    int amt = row>>4, arm = row&15;
    int bnt = row>>3, brn = row&7;
    // A word = k8*1024 + (mt*4 + frag)*32 + thr ; frag = (arm>=8) + 2*(q&1)
    uint32_t* Abase = As + ((amt*4 + (arm>>3))*32) + (arm&7)*4;
    // B word = k8*1024 + (nt*2 + frag)*32 + thr ; frag = (q&1)
    uint32_t* Bbase = Bs + (bnt*2)*32 + brn*4;

    for (int k0 = 0; k0 < K; k0 += 32) {
        #pragma unroll
        for (int i = 0; i < 4; i++) {
            int q = qb + i;
            float4 v = *(const float4*)(Aro + k0 + q*4);
            uint4 u;
            asm("cvt.rna.tf32.f32 %0,%1;":"=r"(u.x):"f"(v.x));
            asm("cvt.rna.tf32.f32 %0,%1;":"=r"(u.y):"f"(v.y));
            asm("cvt.rna.tf32.f32 %0,%1;":"=r"(u.z):"f"(v.z));
            asm("cvt.rna.tf32.f32 %0,%1;":"=r"(u.w):"f"(v.w));
            *(uint4*)(Abase + (q>>1)*1024 + (q&1)*64) = u;
        }
        #pragma unroll
        for (int i = 0; i < 4; i++) {
            int q = qb + i;
            float4 v = *(const float4*)(Bro + k0 + q*4);
            uint4 u;
            asm("cvt.rna.tf32.f32 %0,%1;":"=r"(u.x):"f"(v.x));
            asm("cvt.rna.tf32.f32 %0,%1;":"=r"(u.y):"f"(v.y));
            asm("cvt.rna.tf32.f32 %0,%1;":"=r"(u.z):"f"(v.z));
            asm("cvt.rna.tf32.f32 %0,%1;":"=r"(u.w):"f"(v.w));
            *(uint4*)(Bbase + (q>>1)*1024 + (q&1)*32) = u;
        }
        __syncthreads();
        #pragma unroll
        for (int k8 = 0; k8 < 4; k8++) {
            uint32_t a[4][4], b[4][2];
            #pragma unroll
            for (int mt = 0; mt < 4; mt++) {
                const uint32_t* p = As + k8*1024 + ((wm*4+mt)*4)*32 + lane;
                a[mt][0]=p[0]; a[mt][1]=p[32]; a[mt][2]=p[64]; a[mt][3]=p[96];
            }
            #pragma unroll
            for (int nt = 0; nt < 4; nt++) {
                const uint32_t* p = Bs + k8*1024 + ((wn*4+nt)*2)*32 + lane;
                b[nt][0]=p[0]; b[nt][1]=p[32];
            }
            #pragma unroll
            for (int mt = 0; mt < 4; mt++)
                #pragma unroll
                for (int nt = 0; nt < 4; nt++)
                    asm volatile(
                        "mma.sync.aligned.m16n8k8.row.col.f32.tf32.tf32.f32 "
                        "{%0,%1,%2,%3}, {%4,%5,%6,%7}, {%8,%9}, {%0,%1,%2,%3};"
                        : "+f"(c[mt][nt][0]), "+f"(c[mt][nt][1]),
                          "+f"(c[mt][nt][2]), "+f"(c[mt][nt][3])
                        : "r"(a[mt][0]), "r"(a[mt][1]), "r"(a[mt][2]), "r"(a[mt][3]),
                          "r"(b[nt][0]), "r"(b[nt][1]));
        }
        __syncthreads();
    }
    // epilogue
    int g = lane>>2, tg = lane&3;
    #pragma unroll
    for (int mt = 0; mt < 4; mt++) {
        size_t r0 = (size_t)(bm + wm*64 + mt*16 + g);
        size_t r1 = r0 + 8;
        #pragma unroll
        for (int nt = 0; nt < 4; nt++) {
            int col = bn + wn*32 + nt*8 + tg*2;
            float2 v0 = make_float2(alpha*c[mt][nt][0], alpha*c[mt][nt][1]);
            float2 v1 = make_float2(alpha*c[mt][nt][2], alpha*c[mt][nt][3]);
            if (RESID) {
                float2 q0 = *(const float2*)&Rsrc[r0*N + col];
                float2 q1 = *(const float2*)&Rsrc[r1*N + col];
                v0.x += q0.x; v0.y += q0.y; v1.x += q1.x; v1.y += q1.y;
            }
            *(float2*)&C[r0*N + col] = v0;
            *(float2*)&C[r1*N + col] = v1;
        }
    }
}

// ---------------- causal flash attention (fp32, dh=64) ----------------------
__global__ __launch_bounds__(64) void flash_kernel(
    const float* __restrict__ Q, const float* __restrict__ Kt,
    const float* __restrict__ V, float* __restrict__ O)
{
    int qt = blockIdx.x, h = blockIdx.y, b = blockIdx.z;
    int t = threadIdx.x;
    int qr = qt*64 + t;
    const size_t base = ((size_t)b*Ssz)*Dsz + h*DHsz;

    float q[64];
    #pragma unroll
    for (int i = 0; i < 16; i++) {
        float4 v = *(const float4*)&Q[base + (size_t)qr*Dsz + i*4];
        q[4*i+0] = v.x*0.125f; q[4*i+1] = v.y*0.125f;
        q[4*i+2] = v.z*0.125f; q[4*i+3] = v.w*0.125f;
    }
    float acc[64];
    #pragma unroll
    for (int i = 0; i < 64; i++) acc[i] = 0.f;
    float m = -1e30f, l = 0.f;

    __shared__ float Ks[32][64];
    __shared__ float Vs[32][64];

    int ntiles = qt*2 + 2;
    for (int kt = 0; kt < ntiles; kt++) {
        int k0 = kt*32;
        #pragma unroll
        for (int i = 0; i < 8; i++) {
            int idx = t + i*64;
            int row = idx >> 4, col4 = (idx & 15)*4;
            *(float4*)&Ks[row][col4] = *(const float4*)&Kt[base + (size_t)(k0+row)*Dsz + col4];
            *(float4*)&Vs[row][col4] = *(const float4*)&V [base + (size_t)(k0+row)*Dsz + col4];
        }
        __syncthreads();

        float s[32];
        float mnew = m;
        #pragma unroll
        for (int k = 0; k < 32; k++) {
            float d0 = 0.f, d1 = 0.f, d2 = 0.f, d3 = 0.f;
            #pragma unroll
            for (int i = 0; i < 16; i++) {
                float4 kv = *(const float4*)&Ks[k][i*4];
                d0 = fmaf(q[4*i+0], kv.x, d0);
                d1 = fmaf(q[4*i+1], kv.y, d1);
                d2 = fmaf(q[4*i+2], kv.z, d2);
                d3 = fmaf(q[4*i+3], kv.w, d3);
            }
            float d = (d0+d1)+(d2+d3);
            d = (k0 + k > qr) ? -1e30f : d;
            s[k] = d;
            mnew = fmaxf(mnew, d);
        }
        float corr = __expf(m - mnew);
        l *= corr;
        #pragma unroll
        for (int i = 0; i < 64; i++) acc[i] *= corr;
        #pragma unroll
        for (int k = 0; k < 32; k++) {
            float p = __expf(s[k] - mnew);
            l += p;
            #pragma unroll
            for (int i = 0; i < 16; i++) {
                float4 vv = *(const float4*)&Vs[k][i*4];
                acc[4*i+0] = fmaf(p, vv.x, acc[4*i+0]);
                acc[4*i+1] = fmaf(p, vv.y, acc[4*i+1]);
                acc[4*i+2] = fmaf(p, vv.z, acc[4*i+2]);
                acc[4*i+3] = fmaf(p, vv.w, acc[4*i+3]);
            }
        }
        m = mnew;
        __syncthreads();
    }
    float inv = 1.f / l;
    #pragma unroll
    for (int i = 0; i < 16; i++) {
        float4 r;
        r.x = acc[4*i+0]*inv; r.y = acc[4*i+1]*inv;
        r.z = acc[4*i+2]*inv; r.w = acc[4*i+3]*inv;
        *(float4*)&O[base + (size_t)qr*Dsz + i*4] = r;
    }
}

// ---------------- top-8 + softmax + knowledge gather + residual add ---------
__global__ __launch_bounds__(256) void topk_mem_kernel(
    const float* __restrict__ MS, const float* __restrict__ KV,
    float* __restrict__ OUT)
{
    int s = blockIdx.x, b = blockIdx.y, tid = threadIdx.x;
    __shared__ float sc[NKk];
    __shared__ float rv[256];
    __shared__ int   ri[256];
    __shared__ float topv[8];
    __shared__ int   topi[8];
    __shared__ float tw[8];
    const float* row = MS + ((size_t)b*Ssz + s)*NKk;
    for (int i = tid; i < NKk; i += 256) sc[i] = row[i];
    __syncthreads();
    for (int it = 0; it < 8; it++) {
        float bv = -1e30f; int bi = NKk;
        for (int i = tid; i < NKk; i += 256) {
            float v = sc[i];
            if (v > bv) { bv = v; bi = i; }
        }
        rv[tid] = bv; ri[tid] = bi;
        __syncthreads();
        for (int off = 128; off > 0; off >>= 1) {
            if (tid < off) {
                if (rv[tid+off] > rv[tid] ||
                    (rv[tid+off] == rv[tid] && ri[tid+off] < ri[tid])) {
                    rv[tid] = rv[tid+off]; ri[tid] = ri[tid+off];
                }
            }
            __syncthreads();
        }
        if (tid == 0) { topv[it] = rv[0]; topi[it] = ri[0]; sc[ri[0]] = -1e30f; }
        __syncthreads();
    }
    if (tid == 0) {
        float mx = topv[0]; float se = 0.f;
        #pragma unroll
        for (int k = 0; k < 8; k++) { tw[k] = __expf(topv[k]-mx); se += tw[k]; }
        float inv = 1.f/se;
        #pragma unroll
        for (int k = 0; k < 8; k++) tw[k] *= inv;
    }
    __syncthreads();
    float w0 = tw[0], w1 = tw[1], w2 = tw[2], w3 = tw[3];
    float w4 = tw[4], w5 = tw[5], w6 = tw[6], w7 = tw[7];
    size_t i0 = (size_t)topi[0]*Dsz, i1 = (size_t)topi[1]*Dsz;
    size_t i2 = (size_t)topi[2]*Dsz, i3 = (size_t)topi[3]*Dsz;
    size_t i4 = (size_t)topi[4]*Dsz, i5 = (size_t)topi[5]*Dsz;
    size_t i6 = (size_t)topi[6]*Dsz, i7 = (size_t)topi[7]*Dsz;
    float* o = OUT + ((size_t)b*Ssz + s)*Dsz;
    for (int d = tid; d < Dsz; d += 256) {
        float a = o[d];
        a = fmaf(w0, KV[i0+d], a); a = fmaf(w1, KV[i1+d], a);
        a = fmaf(w2, KV[i2+d], a); a = fmaf(w3, KV[i3+d], a);
        a = fmaf(w4, KV[i4+d], a); a = fmaf(w5, KV[i5+d], a);
        a = fmaf(w6, KV[i6+d], a); a = fmaf(w7, KV[i7+d], a);
        o[d] = a;
    }
}

// ---------------- launch ----------------------------------------------------
extern "C" void kernel_launch(void* const* d_in, const int* in_sizes, int n_in,
                              void* d_out, int out_size)
{
    const float* x    = (const float*)d_in[0];
    const float* imp  = (const float*)d_in[1];
    const float* Wc   = (const float*)d_in[2];
    const float* WQ   = (const float*)d_in[3];
    const float* WK   = (const float*)d_in[4];
    const float* WV   = (const float*)d_in[5];
    const float* Wm   = (const float*)d_in[6];
    const float* cn   = (const float*)d_in[7];
    const float* pool = (const float*)d_in[8];
    const float* kK   = (const float*)d_in[9];
    const float* kV   = (const float*)d_in[10];
    const float* WO   = (const float*)d_in[11];
    const float* g1   = (const float*)d_in[12];
    const float* b1   = (const float*)d_in[13];
    const float* g2   = (const float*)d_in[14];
    const float* b2   = (const float*)d_in[15];
    float* out = (float*)d_out;

    static float* base = nullptr;
    if (!base) cudaGetSymbolAddress((void**)&base, g_scratch);

    float* nx   = base + OFF_NX;
    float* nx2  = base + OFF_NX2;
    float* scp  = base + OFF_SC;
    float* mcp  = base + OFF_MC;
    float* ep   = base + OFF_E;
    float* hp   = base + OFF_H;
    float* qmp  = base + OFF_QM;
    float* qkvp = base + OFF_QKV;
    float* aop  = base + OFF_AO;
    float* msp  = base + OFF_MS;
    float* accP = base + OFF_ACC;
    float* wptr = base + OFF_W;

    const size_t SD = (size_t)Ssz*Dsz;
    const size_t SR = (size_t)Ssz*Rsz;
    const size_t DR = (size_t)Dsz*Rsz;
    const size_t RD = (size_t)Rsz*Dsz;
    const size_t BSD = (size_t)Bsz*Ssz*Dsz;
    const size_t SNK = (size_t)Ssz*NKk;

    // 1) zero router accumulators
    zero_kernel<<<(NSLICE*Bsz*5*16 + 255)/256, 256>>>(accP, NSLICE*Bsz*5*16);
    // 2) LN1 + 4 routers
    ln_route_kernel<<<dim3(Ssz, Bsz), 256>>>(x, imp, Wc, WQ, WK, WV, g1, b1,
                                             nx, accP, 4, 0);
    finalize_w_kernel<<<1, 256>>>(accP, wptr, 0, 4);
    // 3) scT [B][R][D], eT [3*B][D][R]
    combine_cT_kernel<<<dim3(Dsz/32, Rsz/32), 256>>>(wptr, cn, scp, 0);
    combine_eT_kernel<<<dim3(Dsz/32, Rsz/32), 256>>>(wptr, pool, ep);
    // 4) h = nx @ scT^T   [2048,256] : A[2048,1024] x B[256,1024]^T
    tgemm_kernel<false><<<dim3(Rsz/128, Ssz/128, Bsz), 256>>>(nx, scp, nullptr, hp,
        Ssz, Rsz, Dsz, 1.f, SD, RD, SR, 0);
    // 5) Q/K/V = h @ eT^T [2048,1024] : A[2048,256] x B[1024,256]^T
    for (int r3 = 0; r3 < 3; r3++)
        tgemm_kernel<false><<<dim3(Dsz/128, Ssz/128, Bsz), 256>>>(hp,
            ep + (size_t)r3*Bsz*RD, nullptr, qkvp + (size_t)r3*BSD,
            Ssz, Dsz, Rsz, 1.f, SR, RD, SD, 0);
    // 6) attention
    flash_kernel<<<dim3(Ssz/64, Hsz, Bsz), 64>>>(qkvp, qkvp + BSD, qkvp + 2*BSD, aop);
    // 7) out = x + ao @ W_O^T
    tgemm_kernel<true><<<dim3(Dsz/128, Ssz/128, Bsz), 256>>>(aop, WO, x, out,
        Ssz, Dsz, Dsz, 1.f, SD, 0, SD, SD);
    // 8) LN2 + memory router
    ln_route_kernel<<<dim3(Ssz, Bsz), 256>>>(out, imp, Wm, Wm, Wm, Wm, g2, b2,
                                             nx2, accP, 1, 4);
    finalize_w_kernel<<<1, 256>>>(accP, wptr, 4, 1);
    // 9) mcT, Qm
    combine_cT_kernel<<<dim3(Dsz/32, Rsz/32), 256>>>(wptr, cn, mcp, 4);
    tgemm_kernel<false><<<dim3(Rsz/128, Ssz/128, Bsz), 256>>>(nx2, mcp, nullptr, qmp,
        Ssz, Rsz, Dsz, 1.f, SD, RD, SR, 0);
    // 10) ms = Qm @ knowledge_K^T / 16
    tgemm_kernel<false><<<dim3(NKk/128, Ssz/128, Bsz), 256>>>(qmp, kK, nullptr, msp,
        Ssz, NKk, Rsz, 0.0625f, SR, 0, SNK, 0);
    // 11) top-8 + gather + residual
    topk_mem_kernel<<<dim3(Ssz, Bsz), 256>>>(msp, kV, out);
}

// round 6
// speedup vs baseline: 2.5308x; 1.9508x over previous
#include <cuda_runtime.h>
#include <cuda_bf16.h>
#include <math.h>
#include <stdint.h>

#define Bsz 2
#define Ssz 2048
#define Dsz 1024
#define Hsz 16
#define DHsz 64
#define Rsz 256
#define NKk 4096
#define NSLICE 32

// ---------------- single scratch arena (one symbol, no allocations) ---------
#define OFF_NX    ((size_t)0)
#define OFF_NX2   (OFF_NX   + (size_t)Bsz*Ssz*Dsz)
#define OFF_SC    (OFF_NX2  + (size_t)Bsz*Ssz*Dsz)
#define OFF_MC    (OFF_SC   + (size_t)Bsz*Dsz*Rsz)
#define OFF_E     (OFF_MC   + (size_t)Bsz*Dsz*Rsz)
#define OFF_H     (OFF_E    + (size_t)3*Bsz*Rsz*Dsz)
#define OFF_QM    (OFF_H    + (size_t)Bsz*Ssz*Rsz)
#define OFF_QKV   (OFF_QM   + (size_t)Bsz*Ssz*Rsz)
#define OFF_AO    (OFF_QKV  + (size_t)3*Bsz*Ssz*Dsz)
#define OFF_MS    (OFF_AO   + (size_t)Bsz*Ssz*Dsz)
#define OFF_ACC   (OFF_MS   + (size_t)Bsz*Ssz*NKk)
#define OFF_W     (OFF_ACC  + (size_t)NSLICE*Bsz*5*16)
#define SCRATCH_TOTAL (OFF_W + (size_t)Bsz*5*16)

__device__ float g_scratch[SCRATCH_TOTAL];

// ---------------- fast exp on FMA pipe (exp2 poly, rel err ~3e-6) -----------
__device__ __forceinline__ float fexp(float x) {
    x = fmaxf(x, -80.f);
    float z = x * 1.4426950408889634f;
    float r = rintf(z);
    float f = z - r;
    float p =            0.0013333558f;
    p = fmaf(p, f, 0.0096181291f);
    p = fmaf(p, f, 0.0555041087f);
    p = fmaf(p, f, 0.2402264791f);
    p = fmaf(p, f, 0.6931472028f);
    p = fmaf(p, f, 1.0f);
    int e = (int)r;
    return __int_as_float(__float_as_int(p) + (e << 23));
}

__device__ __forceinline__ uint32_t pack_bf16x2(float lo, float hi) {
    __nv_bfloat162 t = __floats2bfloat162_rn(lo, hi);
    uint32_t u;
    memcpy(&u, &t, 4);
    return u;
}

// ---------------- zero router accumulators ----------------------------------
__global__ void zero_kernel(float* p, int n) {
    int i = blockIdx.x*256 + threadIdx.x;
    if (i < n) p[i] = 0.f;
}

// ---------------- LayerNorm + router logits + importance-pooled softmax -----
__global__ __launch_bounds__(256) void ln_route_kernel(
    const float* __restrict__ X, const float* __restrict__ imp,
    const float* __restrict__ W0, const float* __restrict__ W1,
    const float* __restrict__ W2, const float* __restrict__ W3,
    const float* __restrict__ gamma, const float* __restrict__ beta,
    float* __restrict__ NX, float* __restrict__ accPart,
    int nR, int rbase)
{
    int s = blockIdx.x, b = blockIdx.y, tid = threadIdx.x;
    int lane = tid & 31, wid = tid >> 5;
    const float* xr = X + ((size_t)b*Ssz + s)*Dsz;
    __shared__ float xs[Dsz];
    __shared__ float red[32];
    __shared__ float lg[64];
    float lsum = 0.f, lsq = 0.f;
    for (int i = tid; i < Dsz; i += 256) {
        float v = xr[i]; xs[i] = v; lsum += v; lsq += v*v;
    }
    #pragma unroll
    for (int o = 16; o > 0; o >>= 1) {
        lsum += __shfl_down_sync(0xffffffffu, lsum, o);
        lsq  += __shfl_down_sync(0xffffffffu, lsq,  o);
    }
    if (lane == 0) { red[wid] = lsum; red[8+wid] = lsq; }
    __syncthreads();
    if (tid == 0) {
        float ssum = 0.f, sq = 0.f;
        #pragma unroll
        for (int w = 0; w < 8; w++) { ssum += red[w]; sq += red[8+w]; }
        float mean = ssum / (float)Dsz;
        float var  = sq / (float)Dsz - mean*mean;
        red[16] = mean; red[17] = rsqrtf(var + 1e-5f);
    }
    __syncthreads();
    float mean = red[16], rstd = red[17];
    float* nxr = NX + ((size_t)b*Ssz + s)*Dsz;
    for (int i = tid; i < Dsz; i += 256) {
        float v = (xs[i]-mean)*rstd*gamma[i] + beta[i];
        xs[i] = v; nxr[i] = v;
    }
    __syncthreads();
    for (int e = wid; e < nR*16; e += 8) {
        const float* Wr = (e < 16 ? W0 : (e < 32 ? W1 : (e < 48 ? W2 : W3))) + (size_t)(e & 15)*Dsz;
        float acc = 0.f;
        for (int i = lane; i < Dsz; i += 32) acc += xs[i]*Wr[i];
        #pragma unroll
        for (int o = 16; o > 0; o >>= 1) acc += __shfl_down_sync(0xffffffffu, acc, o);
        if (lane == 0) lg[e] = acc;
    }
    __syncthreads();
    if (tid < nR) {
        float mx = -1e30f;
        #pragma unroll
        for (int e = 0; e < 16; e++) mx = fmaxf(mx, lg[tid*16+e]);
        float ex[16]; float se = 0.f;
        #pragma unroll
        for (int e = 0; e < 16; e++) { ex[e] = __expf(lg[tid*16+e]-mx); se += ex[e]; }
        float wi = imp[(size_t)b*Ssz + s] / se;
        int slice = s & (NSLICE-1);
        float* dst = accPart + ((size_t)(slice*Bsz + b)*5 + rbase + tid)*16;
        #pragma unroll
        for (int e = 0; e < 16; e++) atomicAdd(&dst[e], wi*ex[e]);
    }
}

// ---------------- reduce slices + normalize route weights -------------------
__global__ void finalize_w_kernel(const float* __restrict__ accPart,
                                  float* __restrict__ w, int rbase, int nR)
{
    __shared__ float vals[2*5*16];
    int t = threadIdx.x;
    int tot = Bsz*nR*16;
    if (t < tot) {
        int b = t/(nR*16); int r = (t/16) % nR; int e = t & 15;
        float sum = 0.f;
        for (int sl = 0; sl < NSLICE; sl++)
            sum += accPart[((size_t)(sl*Bsz + b)*5 + rbase + r)*16 + e];
        vals[t] = sum;
    }
    __syncthreads();
    if (t < tot) {
        int b = t/(nR*16); int r = (t/16) % nR;
        float den = 1e-8f;
        #pragma unroll
        for (int j = 0; j < 16; j++) den += vals[(b*nR + r)*16 + j];
        w[((b*5) + rbase + r)*16 + (t & 15)] = vals[t] / den;
    }
}

// ------- weighted pool combine TRANSPOSED: [16,D,R] -> scT [B][R][D] --------
__global__ __launch_bounds__(256) void combine_cT_kernel(
    const float* __restrict__ w, const float* __restrict__ pool,
    float* __restrict__ out, int router)
{
    __shared__ float ws[2][16];
    __shared__ float tile[2][32][33];
    int tid = threadIdx.x;
    if (tid < 32) ws[tid>>4][tid&15] = w[((tid>>4)*5 + router)*16 + (tid&15)];
    __syncthreads();
    int tx = tid & 31, ty = tid >> 5;
    int d0 = blockIdx.x*32, r0 = blockIdx.y*32;
    const size_t X = (size_t)Dsz*Rsz;
    #pragma unroll
    for (int dr = 0; dr < 4; dr++) {
        int dd = ty + dr*8;
        float a0 = 0.f, a1 = 0.f;
        #pragma unroll
        for (int n = 0; n < 16; n++) {
            float p = pool[(size_t)n*X + (size_t)(d0+dd)*Rsz + r0 + tx];
            a0 += ws[0][n]*p; a1 += ws[1][n]*p;
        }
        tile[0][dd][tx] = a0; tile[1][dd][tx] = a1;
    }
    __syncthreads();
    #pragma unroll
    for (int dr = 0; dr < 4; dr++) {
        int rr = ty + dr*8;
        out[(size_t)(r0+rr)*Dsz + d0 + tx]     = tile[0][tx][rr];
        out[X + (size_t)(r0+rr)*Dsz + d0 + tx] = tile[1][tx][rr];
    }
}

// ------- expand combine TRANSPOSED: [16,R,D] -> eT [3*B][D][R] --------------
__global__ __launch_bounds__(256) void combine_eT_kernel(
    const float* __restrict__ w, const float* __restrict__ pool,
    float* __restrict__ out)
{
    __shared__ float ws[6][16];
    __shared__ float tile[6][32][33];
    int tid = threadIdx.x;
    if (tid < 96) {
        int slot = tid>>4, e = tid&15;
        int r3 = slot>>1, b = slot&1;
        ws[slot][e] = w[(b*5 + 1 + r3)*16 + e];
    }
    __syncthreads();
    int tx = tid&31, ty = tid>>5;
    int d0 = blockIdx.x*32, r0 = blockIdx.y*32;
    const size_t X = (size_t)Rsz*Dsz;
    #pragma unroll
    for (int dr = 0; dr < 4; dr++) {
        int rr = ty + dr*8;
        float a[6] = {0.f,0.f,0.f,0.f,0.f,0.f};
        #pragma unroll
        for (int n = 0; n < 16; n++) {
            float p = pool[(size_t)n*X + (size_t)(r0+rr)*Dsz + d0+tx];
            #pragma unroll
            for (int sl = 0; sl < 6; sl++) a[sl] += ws[sl][n]*p;
        }
        #pragma unroll
        for (int sl = 0; sl < 6; sl++) tile[sl][rr][tx] = a[sl];
    }
    __syncthreads();
    #pragma unroll
    for (int dr = 0; dr < 4; dr++) {
        int dd = ty + dr*8;
        #pragma unroll
        for (int sl = 0; sl < 6; sl++)
            out[(size_t)sl*X + (size_t)(d0+dd)*Rsz + r0+tx] = tile[sl][tx][dd];
    }
}

// ---------------- tf32 tensor-core GEMM (NT): C = alpha*A[M,K] x B[N,K]^T ---
template<bool RESID>
__global__ __launch_bounds__(256) void tgemm_kernel(
    const float* __restrict__ A, const float* __restrict__ Bm,
    const float* __restrict__ Rsrc, float* __restrict__ C,
    int M, int N, int K, float alpha,
    size_t sA, size_t sB, size_t sC, size_t sR)
{
    __shared__ uint32_t As[4*8*4*32];
    __shared__ uint32_t Bs[4*16*2*32];
    A += (size_t)blockIdx.z*sA; Bm += (size_t)blockIdx.z*sB;
    C += (size_t)blockIdx.z*sC; if (RESID) Rsrc += (size_t)blockIdx.z*sR;
    int tid = threadIdx.x, lane = tid&31, warp = tid>>5;
    int wm = warp>>2, wn = warp&3;
    int bm = blockIdx.y<<7, bn = blockIdx.x<<7;

    float c[4][4][4];
    #pragma unroll
    for (int i=0;i<4;i++)
        #pragma unroll
        for(int j=0;j<4;j++)
            #pragma unroll
            for(int f=0;f<4;f++) c[i][j][f]=0.f;

    int row = tid>>1;
    int qb  = (tid&1)*4;
    const float* Aro = A + (size_t)(bm+row)*K;
    const float* Bro = Bm + (size_t)(bn+row)*K;
    int amt = row>>4, arm = row&15;
    int bnt = row>>3, brn = row&7;
    uint32_t* Abase = As + ((amt*4 + (arm>>3))*32) + (arm&7)*4;
    uint32_t* Bbase = Bs + (bnt*2)*32 + brn*4;

    for (int k0 = 0; k0 < K; k0 += 32) {
        #pragma unroll
        for (int i = 0; i < 4; i++) {
            int q = qb + i;
            float4 v = *(const float4*)(Aro + k0 + q*4);
            uint4 u;
            asm("cvt.rna.tf32.f32 %0,%1;":"=r"(u.x):"f"(v.x));
            asm("cvt.rna.tf32.f32 %0,%1;":"=r"(u.y):"f"(v.y));
            asm("cvt.rna.tf32.f32 %0,%1;":"=r"(u.z):"f"(v.z));
            asm("cvt.rna.tf32.f32 %0,%1;":"=r"(u.w):"f"(v.w));
            *(uint4*)(Abase + (q>>1)*1024 + (q&1)*64) = u;
        }
        #pragma unroll
        for (int i = 0; i < 4; i++) {
            int q = qb + i;
            float4 v = *(const float4*)(Bro + k0 + q*4);
            uint4 u;
            asm("cvt.rna.tf32.f32 %0,%1;":"=r"(u.x):"f"(v.x));
            asm("cvt.rna.tf32.f32 %0,%1;":"=r"(u.y):"f"(v.y));
            asm("cvt.rna.tf32.f32 %0,%1;":"=r"(u.z):"f"(v.z));
            asm("cvt.rna.tf32.f32 %0,%1;":"=r"(u.w):"f"(v.w));
            *(uint4*)(Bbase + (q>>1)*1024 + (q&1)*32) = u;
        }
        __syncthreads();
        #pragma unroll
        for (int k8 = 0; k8 < 4; k8++) {
            uint32_t a[4][4], b[4][2];
            #pragma unroll
            for (int mt = 0; mt < 4; mt++) {
                const uint32_t* p = As + k8*1024 + ((wm*4+mt)*4)*32 + lane;
                a[mt][0]=p[0]; a[mt][1]=p[32]; a[mt][2]=p[64]; a[mt][3]=p[96];
            }
            #pragma unroll
            for (int nt = 0; nt < 4; nt++) {
                const uint32_t* p = Bs + k8*1024 + ((wn*4+nt)*2)*32 + lane;
                b[nt][0]=p[0]; b[nt][1]=p[32];
            }
            #pragma unroll
            for (int mt = 0; mt < 4; mt++)
                #pragma unroll
                for (int nt = 0; nt < 4; nt++)
                    asm volatile(
                        "mma.sync.aligned.m16n8k8.row.col.f32.tf32.tf32.f32 "
                        "{%0,%1,%2,%3}, {%4,%5,%6,%7}, {%8,%9}, {%0,%1,%2,%3};"
                        : "+f"(c[mt][nt][0]), "+f"(c[mt][nt][1]),
                          "+f"(c[mt][nt][2]), "+f"(c[mt][nt][3])
                        : "r"(a[mt][0]), "r"(a[mt][1]), "r"(a[mt][2]), "r"(a[mt][3]),
                          "r"(b[nt][0]), "r"(b[nt][1]));
        }
        __syncthreads();
    }
    int g = lane>>2, tg = lane&3;
    #pragma unroll
    for (int mt = 0; mt < 4; mt++) {
        size_t r0 = (size_t)(bm + wm*64 + mt*16 + g);
        size_t r1 = r0 + 8;
        #pragma unroll
        for (int nt = 0; nt < 4; nt++) {
            int col = bn + wn*32 + nt*8 + tg*2;
            float2 v0 = make_float2(alpha*c[mt][nt][0], alpha*c[mt][nt][1]);
            float2 v1 = make_float2(alpha*c[mt][nt][2], alpha*c[mt][nt][3]);
            if (RESID) {
                float2 q0 = *(const float2*)&Rsrc[r0*N + col];
                float2 q1 = *(const float2*)&Rsrc[r1*N + col];
                v0.x += q0.x; v0.y += q0.y; v1.x += q1.x; v1.y += q1.y;
            }
            *(float2*)&C[r0*N + col] = v0;
            *(float2*)&C[r1*N + col] = v1;
        }
    }
}

// ---------------- bf16 tensor-core causal flash attention (dh=64) -----------
__device__ __forceinline__ void mma16816(float* c, const uint32_t* a,
                                         uint32_t b0, uint32_t b1) {
    asm volatile("mma.sync.aligned.m16n8k16.row.col.f32.bf16.bf16.f32 "
        "{%0,%1,%2,%3}, {%4,%5,%6,%7}, {%8,%9}, {%0,%1,%2,%3};"
        : "+f"(c[0]),"+f"(c[1]),"+f"(c[2]),"+f"(c[3])
        : "r"(a[0]),"r"(a[1]),"r"(a[2]),"r"(a[3]), "r"(b0),"r"(b1));
}

__global__ __launch_bounds__(128) void flash_mma_kernel(
    const float* __restrict__ Q, const float* __restrict__ Kt,
    const float* __restrict__ V, float* __restrict__ O)
{
    __shared__ __nv_bfloat16 Ks[64][72];   // [key][d]   (also Q staging)
    __shared__ __nv_bfloat16 Vs[64][72];   // [d][key]   (transposed)
    int qt = blockIdx.x, h = blockIdx.y, b = blockIdx.z;
    int tid = threadIdx.x, lane = tid&31, w = tid>>5;
    int g = lane>>2, tg = lane&3;
    const size_t base = ((size_t)b*Ssz)*Dsz + h*DHsz;
    int qb = qt*64;
    int frow = tid>>1, fd0 = (tid&1)*32;

    {   // stage Q (pre-scaled by 1/8) into Ks
        const float* src = Q + base + (size_t)(qb+frow)*Dsz + fd0;
        #pragma unroll
        for (int j = 0; j < 8; j++) {
            float4 v = *(const float4*)(src + j*4);
            *(__nv_bfloat162*)&Ks[frow][fd0+j*4]   = __floats2bfloat162_rn(v.x*0.125f, v.y*0.125f);
            *(__nv_bfloat162*)&Ks[frow][fd0+j*4+2] = __floats2bfloat162_rn(v.z*0.125f, v.w*0.125f);
        }
    }
    __syncthreads();
    uint32_t qa[4][4];
    #pragma unroll
    for (int ks = 0; ks < 4; ks++) {
        qa[ks][0] = *(const uint32_t*)&Ks[w*16+g  ][ks*16+2*tg];
        qa[ks][1] = *(const uint32_t*)&Ks[w*16+g+8][ks*16+2*tg];
        qa[ks][2] = *(const uint32_t*)&Ks[w*16+g  ][ks*16+2*tg+8];
        qa[ks][3] = *(const uint32_t*)&Ks[w*16+g+8][ks*16+2*tg+8];
    }

    float o[8][4];
    #pragma unroll
    for (int nt = 0; nt < 8; nt++)
        o[nt][0]=o[nt][1]=o[nt][2]=o[nt][3]=0.f;
    float m0=-1e30f, m1=-1e30f, l0=0.f, l1=0.f;
    int row0 = qb + w*16 + g;

    for (int kt = 0; kt <= qt; kt++) {
        int k0 = kt*64;
        __syncthreads();
        {   // fill K tile [key][d], V tile transposed [d][key]
            const float* ksrc = Kt + base + (size_t)(k0+frow)*Dsz + fd0;
            const float* vsrc = V  + base + (size_t)(k0+frow)*Dsz + fd0;
            #pragma unroll
            for (int j = 0; j < 8; j++) {
                float4 kv = *(const float4*)(ksrc + j*4);
                *(__nv_bfloat162*)&Ks[frow][fd0+j*4]   = __floats2bfloat162_rn(kv.x, kv.y);
                *(__nv_bfloat162*)&Ks[frow][fd0+j*4+2] = __floats2bfloat162_rn(kv.z, kv.w);
                float4 vv = *(const float4*)(vsrc + j*4);
                Vs[fd0+j*4  ][frow] = __float2bfloat16(vv.x);
                Vs[fd0+j*4+1][frow] = __float2bfloat16(vv.y);
                Vs[fd0+j*4+2][frow] = __float2bfloat16(vv.z);
                Vs[fd0+j*4+3][frow] = __float2bfloat16(vv.w);
            }
        }
        __syncthreads();

        float sc[8][4];
        #pragma unroll
        for (int nt = 0; nt < 8; nt++) {
            sc[nt][0]=sc[nt][1]=sc[nt][2]=sc[nt][3]=0.f;
            #pragma unroll
            for (int ks = 0; ks < 4; ks++) {
                uint32_t kb0 = *(const uint32_t*)&Ks[nt*8+g][ks*16+2*tg];
                uint32_t kb1 = *(const uint32_t*)&Ks[nt*8+g][ks*16+2*tg+8];
                mma16816(sc[nt], qa[ks], kb0, kb1);
            }
        }
        if (kt == qt) {
            #pragma unroll
            for (int nt = 0; nt < 8; nt++) {
                int col = k0 + nt*8 + 2*tg;
                if (col   > row0)   sc[nt][0] = -1e30f;
                if (col+1 > row0)   sc[nt][1] = -1e30f;
                if (col   > row0+8) sc[nt][2] = -1e30f;
                if (col+1 > row0+8) sc[nt][3] = -1e30f;
            }
        }
        float mx0 = -1e30f, mx1 = -1e30f;
        #pragma unroll
        for (int nt = 0; nt < 8; nt++) {
            mx0 = fmaxf(mx0, fmaxf(sc[nt][0], sc[nt][1]));
            mx1 = fmaxf(mx1, fmaxf(sc[nt][2], sc[nt][3]));
        }
        mx0 = fmaxf(mx0, __shfl_xor_sync(0xffffffffu, mx0, 1));
        mx0 = fmaxf(mx0, __shfl_xor_sync(0xffffffffu, mx0, 2));
        mx1 = fmaxf(mx1, __shfl_xor_sync(0xffffffffu, mx1, 1));
        mx1 = fmaxf(mx1, __shfl_xor_sync(0xffffffffu, mx1, 2));
        float nm0 = fmaxf(m0, mx0), nm1 = fmaxf(m1, mx1);
        float c0 = fexp(m0 - nm0), c1 = fexp(m1 - nm1);
        m0 = nm0; m1 = nm1;

        uint32_t pa[4][4];
        float s0 = 0.f, s1 = 0.f;
        #pragma unroll
        for (int nt = 0; nt < 8; nt++) {
            float e0 = fexp(sc[nt][0]-m0), e1 = fexp(sc[nt][1]-m0);
            float e2 = fexp(sc[nt][2]-m1), e3 = fexp(sc[nt][3]-m1);
            s0 += e0+e1; s1 += e2+e3;
            int ks = nt>>1, hi = (nt&1)*2;
            pa[ks][hi+0] = pack_bf16x2(e0, e1);
            pa[ks][hi+1] = pack_bf16x2(e2, e3);
        }
        s0 += __shfl_xor_sync(0xffffffffu, s0, 1);
        s0 += __shfl_xor_sync(0xffffffffu, s0, 2);
        s1 += __shfl_xor_sync(0xffffffffu, s1, 1);
        s1 += __shfl_xor_sync(0xffffffffu, s1, 2);
        l0 = l0*c0 + s0; l1 = l1*c1 + s1;

        #pragma unroll
        for (int nt = 0; nt < 8; nt++) {
            o[nt][0]*=c0; o[nt][1]*=c0; o[nt][2]*=c1; o[nt][3]*=c1;
            #pragma unroll
            for (int ks = 0; ks < 4; ks++) {
                uint32_t vb0 = *(const uint32_t*)&Vs[nt*8+g][ks*16+2*tg];
                uint32_t vb1 = *(const uint32_t*)&Vs[nt*8+g][ks*16+2*tg+8];
                mma16816(o[nt], pa[ks], vb0, vb1);
            }
        }
    }
    float i0 = 1.f/l0, i1 = 1.f/l1;
    #pragma unroll
    for (int nt = 0; nt < 8; nt++) {
        float2 v0 = make_float2(o[nt][0]*i0, o[nt][1]*i0);
        float2 v1 = make_float2(o[nt][2]*i1, o[nt][3]*i1);
        *(float2*)&O[base + (size_t)row0*Dsz + nt*8 + 2*tg]     = v0;
        *(float2*)&O[base + (size_t)(row0+8)*Dsz + nt*8 + 2*tg] = v1;
    }
}

// ---------------- top-8 + softmax + knowledge gather + residual add ---------
__global__ __launch_bounds__(256) void topk_mem_kernel(
    const float* __restrict__ MS, const float* __restrict__ KV,
    float* __restrict__ OUT)
{
    int s = blockIdx.x, b = blockIdx.y, tid = threadIdx.x;
    __shared__ float sc[NKk];
    __shared__ float rv[256];
    __shared__ int   ri[256];
    __shared__ float topv[8];
    __shared__ int   topi[8];
    __shared__ float tw[8];
    const float* row = MS + ((size_t)b*Ssz + s)*NKk;
    for (int i = tid; i < NKk; i += 256) sc[i] = row[i];
    __syncthreads();
    for (int it = 0; it < 8; it++) {
        float bv = -1e30f; int bi = NKk;
        for (int i = tid; i < NKk; i += 256) {
            float v = sc[i];
            if (v > bv) { bv = v; bi = i; }
        }
        rv[tid] = bv; ri[tid] = bi;
        __syncthreads();
        for (int off = 128; off > 0; off >>= 1) {
            if (tid < off) {
                if (rv[tid+off] > rv[tid] ||
                    (rv[tid+off] == rv[tid] && ri[tid+off] < ri[tid])) {
                    rv[tid] = rv[tid+off]; ri[tid] = ri[tid+off];
                }
            }
            __syncthreads();
        }
        if (tid == 0) { topv[it] = rv[0]; topi[it] = ri[0]; sc[ri[0]] = -1e30f; }
        __syncthreads();
    }
    if (tid == 0) {
        float mx = topv[0]; float se = 0.f;
        #pragma unroll
        for (int k = 0; k < 8; k++) { tw[k] = __expf(topv[k]-mx); se += tw[k]; }
        float inv = 1.f/se;
        #pragma unroll
        for (int k = 0; k < 8; k++) tw[k] *= inv;
    }
    __syncthreads();
    float w0 = tw[0], w1 = tw[1], w2 = tw[2], w3 = tw[3];
    float w4 = tw[4], w5 = tw[5], w6 = tw[6], w7 = tw[7];
    size_t i0 = (size_t)topi[0]*Dsz, i1 = (size_t)topi[1]*Dsz;
    size_t i2 = (size_t)topi[2]*Dsz, i3 = (size_t)topi[3]*Dsz;
    size_t i4 = (size_t)topi[4]*Dsz, i5 = (size_t)topi[5]*Dsz;
    size_t i6 = (size_t)topi[6]*Dsz, i7 = (size_t)topi[7]*Dsz;
    float* o = OUT + ((size_t)b*Ssz + s)*Dsz;
    for (int d = tid; d < Dsz; d += 256) {
        float a = o[d];
        a = fmaf(w0, KV[i0+d], a); a = fmaf(w1, KV[i1+d], a);
        a = fmaf(w2, KV[i2+d], a); a = fmaf(w3, KV[i3+d], a);
        a = fmaf(w4, KV[i4+d], a); a = fmaf(w5, KV[i5+d], a);
        a = fmaf(w6, KV[i6+d], a); a = fmaf(w7, KV[i7+d], a);
        o[d] = a;
    }
}

// ---------------- launch ----------------------------------------------------
extern "C" void kernel_launch(void* const* d_in, const int* in_sizes, int n_in,
                              void* d_out, int out_size)
{
    const float* x    = (const float*)d_in[0];
    const float* imp  = (const float*)d_in[1];
    const float* Wc   = (const float*)d_in[2];
    const float* WQ   = (const float*)d_in[3];
    const float* WK   = (const float*)d_in[4];
    const float* WV   = (const float*)d_in[5];
    const float* Wm   = (const float*)d_in[6];
    const float* cn   = (const float*)d_in[7];
    const float* pool = (const float*)d_in[8];
    const float* kK   = (const float*)d_in[9];
    const float* kV   = (const float*)d_in[10];
    const float* WO   = (const float*)d_in[11];
    const float* g1   = (const float*)d_in[12];
    const float* b1   = (const float*)d_in[13];
    const float* g2   = (const float*)d_in[14];
    const float* b2   = (const float*)d_in[15];
    float* out = (float*)d_out;

    static float* base = nullptr;
    if (!base) cudaGetSymbolAddress((void**)&base, g_scratch);

    float* nx   = base + OFF_NX;
    float* nx2  = base + OFF_NX2;
    float* scp  = base + OFF_SC;
    float* mcp  = base + OFF_MC;
    float* ep   = base + OFF_E;
    float* hp   = base + OFF_H;
    float* qmp  = base + OFF_QM;
    float* qkvp = base + OFF_QKV;
    float* aop  = base + OFF_AO;
    float* msp  = base + OFF_MS;
    float* accP = base + OFF_ACC;
    float* wptr = base + OFF_W;

    const size_t SD = (size_t)Ssz*Dsz;
    const size_t SR = (size_t)Ssz*Rsz;
    const size_t RD = (size_t)Rsz*Dsz;
    const size_t BSD = (size_t)Bsz*Ssz*Dsz;
    const size_t SNK = (size_t)Ssz*NKk;

    zero_kernel<<<(NSLICE*Bsz*5*16 + 255)/256, 256>>>(accP, NSLICE*Bsz*5*16);
    ln_route_kernel<<<dim3(Ssz, Bsz), 256>>>(x, imp, Wc, WQ, WK, WV, g1, b1,
                                             nx, accP, 4, 0);
    finalize_w_kernel<<<1, 256>>>(accP, wptr, 0, 4);
    combine_cT_kernel<<<dim3(Dsz/32, Rsz/32), 256>>>(wptr, cn, scp, 0);
    combine_eT_kernel<<<dim3(Dsz/32, Rsz/32), 256>>>(wptr, pool, ep);
    tgemm_kernel<false><<<dim3(Rsz/128, Ssz/128, Bsz), 256>>>(nx, scp, nullptr, hp,
        Ssz, Rsz, Dsz, 1.f, SD, RD, SR, 0);
    for (int r3 = 0; r3 < 3; r3++)
        tgemm_kernel<false><<<dim3(Dsz/128, Ssz/128, Bsz), 256>>>(hp,
            ep + (size_t)r3*Bsz*RD, nullptr, qkvp + (size_t)r3*BSD,
            Ssz, Dsz, Rsz, 1.f, SR, RD, SD, 0);
    flash_mma_kernel<<<dim3(Ssz/64, Hsz, Bsz), 128>>>(qkvp, qkvp + BSD,
                                                      qkvp + 2*BSD, aop);
    tgemm_kernel<true><<<dim3(Dsz/128, Ssz/128, Bsz), 256>>>(aop, WO, x, out,
        Ssz, Dsz, Dsz, 1.f, SD, 0, SD, SD);
    ln_route_kernel<<<dim3(Ssz, Bsz), 256>>>(out, imp, Wm, Wm, Wm, Wm, g2, b2,
                                             nx2, accP, 1, 4);
    finalize_w_kernel<<<1, 256>>>(accP, wptr, 4, 1);
    combine_cT_kernel<<<dim3(Dsz/32, Rsz/32), 256>>>(wptr, cn, mcp, 4);
    tgemm_kernel<false><<<dim3(Rsz/128, Ssz/128, Bsz), 256>>>(nx2, mcp, nullptr, qmp,
        Ssz, Rsz, Dsz, 1.f, SD, RD, SR, 0);
    tgemm_kernel<false><<<dim3(NKk/128, Ssz/128, Bsz), 256>>>(qmp, kK, nullptr, msp,
        Ssz, NKk, Rsz, 0.0625f, SR, 0, SNK, 0);
    topk_mem_kernel<<<dim3(Ssz, Bsz), 256>>>(msp, kV, out);
}

// round 7
// speedup vs baseline: 2.5366x; 1.0023x over previous
#include <cuda_runtime.h>
#include <cuda_bf16.h>
#include <math.h>
#include <stdint.h>

#define Bsz 2
#define Ssz 2048
#define Dsz 1024
#define Hsz 16
#define DHsz 64
#define Rsz 256
#define NKk 4096
#define NSLICE 32

// ---------------- single scratch arena (one symbol, no allocations) ---------
#define OFF_NX    ((size_t)0)
#define OFF_NX2   (OFF_NX   + (size_t)Bsz*Ssz*Dsz)
#define OFF_SC    (OFF_NX2  + (size_t)Bsz*Ssz*Dsz)
#define OFF_MC    (OFF_SC   + (size_t)Bsz*Dsz*Rsz)
#define OFF_E     (OFF_MC   + (size_t)Bsz*Dsz*Rsz)
#define OFF_H     (OFF_E    + (size_t)3*Bsz*Rsz*Dsz)
#define OFF_QM    (OFF_H    + (size_t)Bsz*Ssz*Rsz)
#define OFF_QKV   (OFF_QM   + (size_t)Bsz*Ssz*Rsz)
#define OFF_AO    (OFF_QKV  + (size_t)3*Bsz*Ssz*Dsz)
#define OFF_MS    (OFF_AO   + (size_t)Bsz*Ssz*Dsz)
#define OFF_ACC   (OFF_MS   + (size_t)Bsz*Ssz*NKk)
#define OFF_W     (OFF_ACC  + (size_t)NSLICE*Bsz*5*16)
#define SCRATCH_TOTAL (OFF_W + (size_t)Bsz*5*16)

__device__ float g_scratch[SCRATCH_TOTAL];

// ---------------- fast exp on FMA pipe (exp2 poly, rel err ~3e-6) -----------
__device__ __forceinline__ float fexp(float x) {
    x = fmaxf(x, -80.f);
    float z = x * 1.4426950408889634f;
    float r = rintf(z);
    float f = z - r;
    float p =            0.0013333558f;
    p = fmaf(p, f, 0.0096181291f);
    p = fmaf(p, f, 0.0555041087f);
    p = fmaf(p, f, 0.2402264791f);
    p = fmaf(p, f, 0.6931472028f);
    p = fmaf(p, f, 1.0f);
    int e = (int)r;
    return __int_as_float(__float_as_int(p) + (e << 23));
}

__device__ __forceinline__ uint32_t pack_bf16x2(float lo, float hi) {
    __nv_bfloat162 t = __floats2bfloat162_rn(lo, hi);
    uint32_t u;
    memcpy(&u, &t, 4);
    return u;
}

// ---------------- zero router accumulators ----------------------------------
__global__ void zero_kernel(float* p, int n) {
    int i = blockIdx.x*256 + threadIdx.x;
    if (i < n) p[i] = 0.f;
}

// ---------------- LayerNorm + router logits + importance-pooled softmax -----
__global__ __launch_bounds__(256) void ln_route_kernel(
    const float* __restrict__ X, const float* __restrict__ imp,
    const float* __restrict__ W0, const float* __restrict__ W1,
    const float* __restrict__ W2, const float* __restrict__ W3,
    const float* __restrict__ gamma, const float* __restrict__ beta,
    float* __restrict__ NX, float* __restrict__ accPart,
    int nR, int rbase)
{
    int s = blockIdx.x, b = blockIdx.y, tid = threadIdx.x;
    int lane = tid & 31, wid = tid >> 5;
    const float* xr = X + ((size_t)b*Ssz + s)*Dsz;
    __shared__ float xs[Dsz];
    __shared__ float red[32];
    __shared__ float lg[64];
    float lsum = 0.f, lsq = 0.f;
    for (int i = tid; i < Dsz; i += 256) {
        float v = xr[i]; xs[i] = v; lsum += v; lsq += v*v;
    }
    #pragma unroll
    for (int o = 16; o > 0; o >>= 1) {
        lsum += __shfl_down_sync(0xffffffffu, lsum, o);
        lsq  += __shfl_down_sync(0xffffffffu, lsq,  o);
    }
    if (lane == 0) { red[wid] = lsum; red[8+wid] = lsq; }
    __syncthreads();
    if (tid == 0) {
        float ssum = 0.f, sq = 0.f;
        #pragma unroll
        for (int w = 0; w < 8; w++) { ssum += red[w]; sq += red[8+w]; }
        float mean = ssum / (float)Dsz;
        float var  = sq / (float)Dsz - mean*mean;
        red[16] = mean; red[17] = rsqrtf(var + 1e-5f);
    }
    __syncthreads();
    float mean = red[16], rstd = red[17];
    float* nxr = NX + ((size_t)b*Ssz + s)*Dsz;
    for (int i = tid; i < Dsz; i += 256) {
        float v = (xs[i]-mean)*rstd*gamma[i] + beta[i];
        xs[i] = v; nxr[i] = v;
    }
    __syncthreads();
    for (int e = wid; e < nR*16; e += 8) {
        const float* Wr = (e < 16 ? W0 : (e < 32 ? W1 : (e < 48 ? W2 : W3))) + (size_t)(e & 15)*Dsz;
        float acc = 0.f;
        for (int i = lane; i < Dsz; i += 32) acc += xs[i]*Wr[i];
        #pragma unroll
        for (int o = 16; o > 0; o >>= 1) acc += __shfl_down_sync(0xffffffffu, acc, o);
        if (lane == 0) lg[e] = acc;
    }
    __syncthreads();
    if (tid < nR) {
        float mx = -1e30f;
        #pragma unroll
        for (int e = 0; e < 16; e++) mx = fmaxf(mx, lg[tid*16+e]);
        float ex[16]; float se = 0.f;
        #pragma unroll
        for (int e = 0; e < 16; e++) { ex[e] = __expf(lg[tid*16+e]-mx); se += ex[e]; }
        float wi = imp[(size_t)b*Ssz + s] / se;
        int slice = s & (NSLICE-1);
        float* dst = accPart + ((size_t)(slice*Bsz + b)*5 + rbase + tid)*16;
        #pragma unroll
        for (int e = 0; e < 16; e++) atomicAdd(&dst[e], wi*ex[e]);
    }
}

// ---------------- reduce slices + normalize route weights -------------------
__global__ void finalize_w_kernel(const float* __restrict__ accPart,
                                  float* __restrict__ w, int rbase, int nR)
{
    __shared__ float vals[2*5*16];
    int t = threadIdx.x;
    int tot = Bsz*nR*16;
    if (t < tot) {
        int b = t/(nR*16); int r = (t/16) % nR; int e = t & 15;
        float sum = 0.f;
        for (int sl = 0; sl < NSLICE; sl++)
            sum += accPart[((size_t)(sl*Bsz + b)*5 + rbase + r)*16 + e];
        vals[t] = sum;
    }
    __syncthreads();
    if (t < tot) {
        int b = t/(nR*16); int r = (t/16) % nR;
        float den = 1e-8f;
        #pragma unroll
        for (int j = 0; j < 16; j++) den += vals[(b*nR + r)*16 + j];
        w[((b*5) + rbase + r)*16 + (t & 15)] = vals[t] / den;
    }
}

// ------- weighted pool combine TRANSPOSED: [16,D,R] -> scT [B][R][D] --------
__global__ __launch_bounds__(256) void combine_cT_kernel(
    const float* __restrict__ w, const float* __restrict__ pool,
    float* __restrict__ out, int router)
{
    __shared__ float ws[2][16];
    __shared__ float tile[2][32][33];
    int tid = threadIdx.x;
    if (tid < 32) ws[tid>>4][tid&15] = w[((tid>>4)*5 + router)*16 + (tid&15)];
    __syncthreads();
    int tx = tid & 31, ty = tid >> 5;
    int d0 = blockIdx.x*32, r0 = blockIdx.y*32;
    const size_t X = (size_t)Dsz*Rsz;
    #pragma unroll
    for (int dr = 0; dr < 4; dr++) {
        int dd = ty + dr*8;
        float a0 = 0.f, a1 = 0.f;
        #pragma unroll
        for (int n = 0; n < 16; n++) {
            float p = pool[(size_t)n*X + (size_t)(d0+dd)*Rsz + r0 + tx];
            a0 += ws[0][n]*p; a1 += ws[1][n]*p;
        }
        tile[0][dd][tx] = a0; tile[1][dd][tx] = a1;
    }
    __syncthreads();
    #pragma unroll
    for (int dr = 0; dr < 4; dr++) {
        int rr = ty + dr*8;
        out[(size_t)(r0+rr)*Dsz + d0 + tx]     = tile[0][tx][rr];
        out[X + (size_t)(r0+rr)*Dsz + d0 + tx] = tile[1][tx][rr];
    }
}

// ------- expand combine TRANSPOSED: [16,R,D] -> eT [3*B][D][R] --------------
__global__ __launch_bounds__(256) void combine_eT_kernel(
    const float* __restrict__ w, const float* __restrict__ pool,
    float* __restrict__ out)
{
    __shared__ float ws[6][16];
    __shared__ float tile[6][32][33];
    int tid = threadIdx.x;
    if (tid < 96) {
        int slot = tid>>4, e = tid&15;
        int r3 = slot>>1, b = slot&1;
        ws[slot][e] = w[(b*5 + 1 + r3)*16 + e];
    }
    __syncthreads();
    int tx = tid&31, ty = tid>>5;
    int d0 = blockIdx.x*32, r0 = blockIdx.y*32;
    const size_t X = (size_t)Rsz*Dsz;
    #pragma unroll
    for (int dr = 0; dr < 4; dr++) {
        int rr = ty + dr*8;
        float a[6] = {0.f,0.f,0.f,0.f,0.f,0.f};
        #pragma unroll
        for (int n = 0; n < 16; n++) {
            float p = pool[(size_t)n*X + (size_t)(r0+rr)*Dsz + d0+tx];
            #pragma unroll
            for (int sl = 0; sl < 6; sl++) a[sl] += ws[sl][n]*p;
        }
        #pragma unroll
        for (int sl = 0; sl < 6; sl++) tile[sl][rr][tx] = a[sl];
    }
    __syncthreads();
    #pragma unroll
    for (int dr = 0; dr < 4; dr++) {
        int dd = ty + dr*8;
        #pragma unroll
        for (int sl = 0; sl < 6; sl++)
            out[(size_t)sl*X + (size_t)(d0+dd)*Rsz + r0+tx] = tile[sl][tx][dd];
    }
}

// ---------------- tf32 tensor-core GEMM (NT): C = alpha*A[M,K] x B[N,K]^T ---
template<bool RESID>
__global__ __launch_bounds__(256) void tgemm_kernel(
    const float* __restrict__ A, const float* __restrict__ Bm,
    const float* __restrict__ Rsrc, float* __restrict__ C,
    int M, int N, int K, float alpha,
    size_t sA, size_t sB, size_t sC, size_t sR)
{
    __shared__ uint32_t As[4*8*4*32];
    __shared__ uint32_t Bs[4*16*2*32];
    A += (size_t)blockIdx.z*sA; Bm += (size_t)blockIdx.z*sB;
    C += (size_t)blockIdx.z*sC; if (RESID) Rsrc += (size_t)blockIdx.z*sR;
    int tid = threadIdx.x, lane = tid&31, warp = tid>>5;
    int wm = warp>>2, wn = warp&3;
    int bm = blockIdx.y<<7, bn = blockIdx.x<<7;

    float c[4][4][4];
    #pragma unroll
    for (int i=0;i<4;i++)
        #pragma unroll
        for(int j=0;j<4;j++)
            #pragma unroll
            for(int f=0;f<4;f++) c[i][j][f]=0.f;

    int row = tid>>1;
    int qb  = (tid&1)*4;
    const float* Aro = A + (size_t)(bm+row)*K;
    const float* Bro = Bm + (size_t)(bn+row)*K;
    int amt = row>>4, arm = row&15;
    int bnt = row>>3, brn = row&7;
    uint32_t* Abase = As + ((amt*4 + (arm>>3))*32) + (arm&7)*4;
    uint32_t* Bbase = Bs + (bnt*2)*32 + brn*4;

    for (int k0 = 0; k0 < K; k0 += 32) {
        #pragma unroll
        for (int i = 0; i < 4; i++) {
            int q = qb + i;
            float4 v = *(const float4*)(Aro + k0 + q*4);
            uint4 u;
            asm("cvt.rna.tf32.f32 %0,%1;":"=r"(u.x):"f"(v.x));
            asm("cvt.rna.tf32.f32 %0,%1;":"=r"(u.y):"f"(v.y));
            asm("cvt.rna.tf32.f32 %0,%1;":"=r"(u.z):"f"(v.z));
            asm("cvt.rna.tf32.f32 %0,%1;":"=r"(u.w):"f"(v.w));
            *(uint4*)(Abase + (q>>1)*1024 + (q&1)*64) = u;
        }
        #pragma unroll
        for (int i = 0; i < 4; i++) {
            int q = qb + i;
            float4 v = *(const float4*)(Bro + k0 + q*4);
            uint4 u;
            asm("cvt.rna.tf32.f32 %0,%1;":"=r"(u.x):"f"(v.x));
            asm("cvt.rna.tf32.f32 %0,%1;":"=r"(u.y):"f"(v.y));
            asm("cvt.rna.tf32.f32 %0,%1;":"=r"(u.z):"f"(v.z));
            asm("cvt.rna.tf32.f32 %0,%1;":"=r"(u.w):"f"(v.w));
            *(uint4*)(Bbase + (q>>1)*1024 + (q&1)*32) = u;
        }
        __syncthreads();
        #pragma unroll
        for (int k8 = 0; k8 < 4; k8++) {
            uint32_t a[4][4], b[4][2];
            #pragma unroll
            for (int mt = 0; mt < 4; mt++) {
                const uint32_t* p = As + k8*1024 + ((wm*4+mt)*4)*32 + lane;
                a[mt][0]=p[0]; a[mt][1]=p[32]; a[mt][2]=p[64]; a[mt][3]=p[96];
            }
            #pragma unroll
            for (int nt = 0; nt < 4; nt++) {
                const uint32_t* p = Bs + k8*1024 + ((wn*4+nt)*2)*32 + lane;
                b[nt][0]=p[0]; b[nt][1]=p[32];
            }
            #pragma unroll
            for (int mt = 0; mt < 4; mt++)
                #pragma unroll
                for (int nt = 0; nt < 4; nt++)
                    asm volatile(
                        "mma.sync.aligned.m16n8k8.row.col.f32.tf32.tf32.f32 "
                        "{%0,%1,%2,%3}, {%4,%5,%6,%7}, {%8,%9}, {%0,%1,%2,%3};"
                        : "+f"(c[mt][nt][0]), "+f"(c[mt][nt][1]),
                          "+f"(c[mt][nt][2]), "+f"(c[mt][nt][3])
                        : "r"(a[mt][0]), "r"(a[mt][1]), "r"(a[mt][2]), "r"(a[mt][3]),
                          "r"(b[nt][0]), "r"(b[nt][1]));
        }
        __syncthreads();
    }
    int g = lane>>2, tg = lane&3;
    #pragma unroll
    for (int mt = 0; mt < 4; mt++) {
        size_t r0 = (size_t)(bm + wm*64 + mt*16 + g);
        size_t r1 = r0 + 8;
        #pragma unroll
        for (int nt = 0; nt < 4; nt++) {
            int col = bn + wn*32 + nt*8 + tg*2;
            float2 v0 = make_float2(alpha*c[mt][nt][0], alpha*c[mt][nt][1]);
            float2 v1 = make_float2(alpha*c[mt][nt][2], alpha*c[mt][nt][3]);
            if (RESID) {
                float2 q0 = *(const float2*)&Rsrc[r0*N + col];
                float2 q1 = *(const float2*)&Rsrc[r1*N + col];
                v0.x += q0.x; v0.y += q0.y; v1.x += q1.x; v1.y += q1.y;
            }
            *(float2*)&C[r0*N + col] = v0;
            *(float2*)&C[r1*N + col] = v1;
        }
    }
}

// ---------------- bf16 tensor-core causal flash attention (dh=64) -----------
__device__ __forceinline__ void mma16816(float* c, const uint32_t* a,
                                         uint32_t b0, uint32_t b1) {
    asm volatile("mma.sync.aligned.m16n8k16.row.col.f32.bf16.bf16.f32 "
        "{%0,%1,%2,%3}, {%4,%5,%6,%7}, {%8,%9}, {%0,%1,%2,%3};"
        : "+f"(c[0]),"+f"(c[1]),"+f"(c[2]),"+f"(c[3])
        : "r"(a[0]),"r"(a[1]),"r"(a[2]),"r"(a[3]), "r"(b0),"r"(b1));
}

__global__ __launch_bounds__(128) void flash_mma_kernel(
    const float* __restrict__ Q, const float* __restrict__ Kt,
    const float* __restrict__ V, float* __restrict__ O)
{
    __shared__ __nv_bfloat16 Ks[64][72];   // [key][d]   (also Q staging)
    __shared__ __nv_bfloat16 Vs[64][72];   // [d][key]   (transposed)
    int qt = blockIdx.x, h = blockIdx.y, b = blockIdx.z;
    int tid = threadIdx.x, lane = tid&31, w = tid>>5;
    int g = lane>>2, tg = lane&3;
    const size_t base = ((size_t)b*Ssz)*Dsz + h*DHsz;
    int qb = qt*64;
    int frow = tid>>1, fd0 = (tid&1)*32;

    {   // stage Q (pre-scaled by 1/8) into Ks
        const float* src = Q + base + (size_t)(qb+frow)*Dsz + fd0;
        #pragma unroll
        for (int j = 0; j < 8; j++) {
            float4 v = *(const float4*)(src + j*4);
            *(__nv_bfloat162*)&Ks[frow][fd0+j*4]   = __floats2bfloat162_rn(v.x*0.125f, v.y*0.125f);
            *(__nv_bfloat162*)&Ks[frow][fd0+j*4+2] = __floats2bfloat162_rn(v.z*0.125f, v.w*0.125f);
        }
    }
    __syncthreads();
    uint32_t qa[4][4];
    #pragma unroll
    for (int ks = 0; ks < 4; ks++) {
        qa[ks][0] = *(const uint32_t*)&Ks[w*16+g  ][ks*16+2*tg];
        qa[ks][1] = *(const uint32_t*)&Ks[w*16+g+8][ks*16+2*tg];
        qa[ks][2] = *(const uint32_t*)&Ks[w*16+g  ][ks*16+2*tg+8];
        qa[ks][3] = *(const uint32_t*)&Ks[w*16+g+8][ks*16+2*tg+8];
    }

    float o[8][4];
    #pragma unroll
    for (int nt = 0; nt < 8; nt++)
        o[nt][0]=o[nt][1]=o[nt][2]=o[nt][3]=0.f;
    float m0=-1e30f, m1=-1e30f, l0=0.f, l1=0.f;
    int row0 = qb + w*16 + g;

    for (int kt = 0; kt <= qt; kt++) {
        int k0 = kt*64;
        __syncthreads();
        {   // fill K tile [key][d], V tile transposed [d][key]
            const float* ksrc = Kt + base + (size_t)(k0+frow)*Dsz + fd0;
            const float* vsrc = V  + base + (size_t)(k0+frow)*Dsz + fd0;
            #pragma unroll
            for (int j = 0; j < 8; j++) {
                float4 kv = *(const float4*)(ksrc + j*4);
                *(__nv_bfloat162*)&Ks[frow][fd0+j*4]   = __floats2bfloat162_rn(kv.x, kv.y);
                *(__nv_bfloat162*)&Ks[frow][fd0+j*4+2] = __floats2bfloat162_rn(kv.z, kv.w);
                float4 vv = *(const float4*)(vsrc + j*4);
                Vs[fd0+j*4  ][frow] = __float2bfloat16(vv.x);
                Vs[fd0+j*4+1][frow] = __float2bfloat16(vv.y);
                Vs[fd0+j*4+2][frow] = __float2bfloat16(vv.z);
                Vs[fd0+j*4+3][frow] = __float2bfloat16(vv.w);
            }
        }
        __syncthreads();

        float sc[8][4];
        #pragma unroll
        for (int nt = 0; nt < 8; nt++) {
            sc[nt][0]=sc[nt][1]=sc[nt][2]=sc[nt][3]=0.f;
            #pragma unroll
            for (int ks = 0; ks < 4; ks++) {
                uint32_t kb0 = *(const uint32_t*)&Ks[nt*8+g][ks*16+2*tg];
                uint32_t kb1 = *(const uint32_t*)&Ks[nt*8+g][ks*16+2*tg+8];
                mma16816(sc[nt], qa[ks], kb0, kb1);
            }
        }
        if (kt == qt) {
            #pragma unroll
            for (int nt = 0; nt < 8; nt++) {
                int col = k0 + nt*8 + 2*tg;
                if (col   > row0)   sc[nt][0] = -1e30f;
                if (col+1 > row0)   sc[nt][1] = -1e30f;
                if (col   > row0+8) sc[nt][2] = -1e30f;
                if (col+1 > row0+8) sc[nt][3] = -1e30f;
            }
        }
        float mx0 = -1e30f, mx1 = -1e30f;
        #pragma unroll
        for (int nt = 0; nt < 8; nt++) {
            mx0 = fmaxf(mx0, fmaxf(sc[nt][0], sc[nt][1]));
            mx1 = fmaxf(mx1, fmaxf(sc[nt][2], sc[nt][3]));
        }
        mx0 = fmaxf(mx0, __shfl_xor_sync(0xffffffffu, mx0, 1));
        mx0 = fmaxf(mx0, __shfl_xor_sync(0xffffffffu, mx0, 2));
        mx1 = fmaxf(mx1, __shfl_xor_sync(0xffffffffu, mx1, 1));
        mx1 = fmaxf(mx1, __shfl_xor_sync(0xffffffffu, mx1, 2));
        float nm0 = fmaxf(m0, mx0), nm1 = fmaxf(m1, mx1);
        float c0 = fexp(m0 - nm0), c1 = fexp(m1 - nm1);
        m0 = nm0; m1 = nm1;

        uint32_t pa[4][4];
        float s0 = 0.f, s1 = 0.f;
        #pragma unroll
        for (int nt = 0; nt < 8; nt++) {
            float e0 = fexp(sc[nt][0]-m0), e1 = fexp(sc[nt][1]-m0);
            float e2 = fexp(sc[nt][2]-m1), e3 = fexp(sc[nt][3]-m1);
            s0 += e0+e1; s1 += e2+e3;
            int ks = nt>>1, hi = (nt&1)*2;
            pa[ks][hi+0] = pack_bf16x2(e0, e1);
            pa[ks][hi+1] = pack_bf16x2(e2, e3);
        }
        s0 += __shfl_xor_sync(0xffffffffu, s0, 1);
        s0 += __shfl_xor_sync(0xffffffffu, s0, 2);
        s1 += __shfl_xor_sync(0xffffffffu, s1, 1);
        s1 += __shfl_xor_sync(0xffffffffu, s1, 2);
        l0 = l0*c0 + s0; l1 = l1*c1 + s1;

        #pragma unroll
        for (int nt = 0; nt < 8; nt++) {
            o[nt][0]*=c0; o[nt][1]*=c0; o[nt][2]*=c1; o[nt][3]*=c1;
            #pragma unroll
            for (int ks = 0; ks < 4; ks++) {
                uint32_t vb0 = *(const uint32_t*)&Vs[nt*8+g][ks*16+2*tg];
                uint32_t vb1 = *(const uint32_t*)&Vs[nt*8+g][ks*16+2*tg+8];
                mma16816(o[nt], pa[ks], vb0, vb1);
            }
        }
    }
    float i0 = 1.f/l0, i1 = 1.f/l1;
    #pragma unroll
    for (int nt = 0; nt < 8; nt++) {
        float2 v0 = make_float2(o[nt][0]*i0, o[nt][1]*i0);
        float2 v1 = make_float2(o[nt][2]*i1, o[nt][3]*i1);
        *(float2*)&O[base + (size_t)row0*Dsz + nt*8 + 2*tg]     = v0;
        *(float2*)&O[base + (size_t)(row0+8)*Dsz + nt*8 + 2*tg] = v1;
    }
}

// ---------------- top-8 + softmax + knowledge gather + residual add ---------
__global__ __launch_bounds__(256) void topk_mem_kernel(
    const float* __restrict__ MS, const float* __restrict__ KV,
    float* __restrict__ OUT)
{
    int s = blockIdx.x, b = blockIdx.y, tid = threadIdx.x;
    __shared__ float sc[NKk];
    __shared__ float rv[256];
    __shared__ int   ri[256];
    __shared__ float topv[8];
    __shared__ int   topi[8];
    __shared__ float tw[8];
    const float* row = MS + ((size_t)b*Ssz + s)*NKk;
    for (int i = tid; i < NKk; i += 256) sc[i] = row[i];
    __syncthreads();
    for (int it = 0; it < 8; it++) {
        float bv = -1e30f; int bi = NKk;
        for (int i = tid; i < NKk; i += 256) {
            float v = sc[i];
            if (v > bv) { bv = v; bi = i; }
        }
        rv[tid] = bv; ri[tid] = bi;
        __syncthreads();
        for (int off = 128; off > 0; off >>= 1) {
            if (tid < off) {
                if (rv[tid+off] > rv[tid] ||
                    (rv[tid+off] == rv[tid] && ri[tid+off] < ri[tid])) {
                    rv[tid] = rv[tid+off]; ri[tid] = ri[tid+off];
                }
            }
            __syncthreads();
        }
        if (tid == 0) { topv[it] = rv[0]; topi[it] = ri[0]; sc[ri[0]] = -1e30f; }
        __syncthreads();
    }
    if (tid == 0) {
        float mx = topv[0]; float se = 0.f;
        #pragma unroll
        for (int k = 0; k < 8; k++) { tw[k] = __expf(topv[k]-mx); se += tw[k]; }
        float inv = 1.f/se;
        #pragma unroll
        for (int k = 0; k < 8; k++) tw[k] *= inv;
    }
    __syncthreads();
    float w0 = tw[0], w1 = tw[1], w2 = tw[2], w3 = tw[3];
    float w4 = tw[4], w5 = tw[5], w6 = tw[6], w7 = tw[7];
    size_t i0 = (size_t)topi[0]*Dsz, i1 = (size_t)topi[1]*Dsz;
    size_t i2 = (size_t)topi[2]*Dsz, i3 = (size_t)topi[3]*Dsz;
    size_t i4 = (size_t)topi[4]*Dsz, i5 = (size_t)topi[5]*Dsz;
    size_t i6 = (size_t)topi[6]*Dsz, i7 = (size_t)topi[7]*Dsz;
    float* o = OUT + ((size_t)b*Ssz + s)*Dsz;
    for (int d = tid; d < Dsz; d += 256) {
        float a = o[d];
        a = fmaf(w0, KV[i0+d], a); a = fmaf(w1, KV[i1+d], a);
        a = fmaf(w2, KV[i2+d], a); a = fmaf(w3, KV[i3+d], a);
        a = fmaf(w4, KV[i4+d], a); a = fmaf(w5, KV[i5+d], a);
        a = fmaf(w6, KV[i6+d], a); a = fmaf(w7, KV[i7+d], a);
        o[d] = a;
    }
}

// ---------------- launch ----------------------------------------------------
extern "C" void kernel_launch(void* const* d_in, const int* in_sizes, int n_in,
                              void* d_out, int out_size)
{
    const float* x    = (const float*)d_in[0];
    const float* imp  = (const float*)d_in[1];
    const float* Wc   = (const float*)d_in[2];
    const float* WQ   = (const float*)d_in[3];
    const float* WK   = (const float*)d_in[4];
    const float* WV   = (const float*)d_in[5];
    const float* Wm   = (const float*)d_in[6];
    const float* cn   = (const float*)d_in[7];
    const float* pool = (const float*)d_in[8];
    const float* kK   = (const float*)d_in[9];
    const float* kV   = (const float*)d_in[10];
    const float* WO   = (const float*)d_in[11];
    const float* g1   = (const float*)d_in[12];
    const float* b1   = (const float*)d_in[13];
    const float* g2   = (const float*)d_in[14];
    const float* b2   = (const float*)d_in[15];
    float* out = (float*)d_out;

    static float* base = nullptr;
    if (!base) cudaGetSymbolAddress((void**)&base, g_scratch);

    float* nx   = base + OFF_NX;
    float* nx2  = base + OFF_NX2;
    float* scp  = base + OFF_SC;
    float* mcp  = base + OFF_MC;
    float* ep   = base + OFF_E;
    float* hp   = base + OFF_H;
    float* qmp  = base + OFF_QM;
    float* qkvp = base + OFF_QKV;
    float* aop  = base + OFF_AO;
    float* msp  = base + OFF_MS;
    float* accP = base + OFF_ACC;
    float* wptr = base + OFF_W;

    const size_t SD = (size_t)Ssz*Dsz;
    const size_t SR = (size_t)Ssz*Rsz;
    const size_t RD = (size_t)Rsz*Dsz;
    const size_t BSD = (size_t)Bsz*Ssz*Dsz;
    const size_t SNK = (size_t)Ssz*NKk;

    zero_kernel<<<(NSLICE*Bsz*5*16 + 255)/256, 256>>>(accP, NSLICE*Bsz*5*16);
    ln_route_kernel<<<dim3(Ssz, Bsz), 256>>>(x, imp, Wc, WQ, WK, WV, g1, b1,
                                             nx, accP, 4, 0);
    finalize_w_kernel<<<1, 256>>>(accP, wptr, 0, 4);
    combine_cT_kernel<<<dim3(Dsz/32, Rsz/32), 256>>>(wptr, cn, scp, 0);
    combine_eT_kernel<<<dim3(Dsz/32, Rsz/32), 256>>>(wptr, pool, ep);
    tgemm_kernel<false><<<dim3(Rsz/128, Ssz/128, Bsz), 256>>>(nx, scp, nullptr, hp,
        Ssz, Rsz, Dsz, 1.f, SD, RD, SR, 0);
    for (int r3 = 0; r3 < 3; r3++)
        tgemm_kernel<false><<<dim3(Dsz/128, Ssz/128, Bsz), 256>>>(hp,
            ep + (size_t)r3*Bsz*RD, nullptr, qkvp + (size_t)r3*BSD,
            Ssz, Dsz, Rsz, 1.f, SR, RD, SD, 0);
    flash_mma_kernel<<<dim3(Ssz/64, Hsz, Bsz), 128>>>(qkvp, qkvp + BSD,
                                                      qkvp + 2*BSD, aop);
    tgemm_kernel<true><<<dim3(Dsz/128, Ssz/128, Bsz), 256>>>(aop, WO, x, out,
        Ssz, Dsz, Dsz, 1.f, SD, 0, SD, SD);
    ln_route_kernel<<<dim3(Ssz, Bsz), 256>>>(out, imp, Wm, Wm, Wm, Wm, g2, b2,
                                             nx2, accP, 1, 4);
    finalize_w_kernel<<<1, 256>>>(accP, wptr, 4, 1);
    combine_cT_kernel<<<dim3(Dsz/32, Rsz/32), 256>>>(wptr, cn, mcp, 4);
    tgemm_kernel<false><<<dim3(Rsz/128, Ssz/128, Bsz), 256>>>(nx2, mcp, nullptr, qmp,
        Ssz, Rsz, Dsz, 1.f, SD, RD, SR, 0);
    tgemm_kernel<false><<<dim3(NKk/128, Ssz/128, Bsz), 256>>>(qmp, kK, nullptr, msp,
        Ssz, NKk, Rsz, 0.0625f, SR, 0, SNK, 0);
    topk_mem_kernel<<<dim3(Ssz, Bsz), 256>>>(msp, kV, out);
}